// round 1
// baseline (speedup 1.0000x reference)
#include <cuda_runtime.h>
#include <cstddef>

// Problem dims (fixed)
#define BB 16
#define SS 2048
#define LL 256
#define HH 768
#define CC 512
#define MROWS (BB*SS)   // 32768

// ---------------- scratch (static device memory; no runtime alloc) ----------
constexpr size_t N_BSC  = (size_t)MROWS * CC;       // 16,777,216
constexpr size_t N_BSL  = (size_t)MROWS * LL;       // 8,388,608
constexpr size_t OFF_IT   = 0;
constexpr size_t OFF_IA   = OFF_IT + N_BSC;
constexpr size_t OFF_W    = OFF_IA + N_BSC;
constexpr size_t OFF_ATTN = OFF_W  + N_BSC;
constexpr size_t OFF_LT   = OFF_ATTN + N_BSL;
constexpr size_t OFF_LA   = OFF_LT + (size_t)LL * CC;
constexpr size_t OFF_FP   = OFF_LA + (size_t)LL * CC;
constexpr size_t OFF_FU   = OFF_FP + (size_t)BB * 32 * CC;
constexpr size_t SCRATCH_ELEMS = OFF_FU + (size_t)BB * CC;

__device__ float g_scratch[SCRATCH_ELEMS];

// ---------------- tiled fp32 GEMM: C[m,n] = op( sum_k A[m,k] * B(n,k) ) -----
// BM=BN=64, BK=16, 256 threads, 4x4 register microtile per thread.
// B_KN=false: B stored [N,K] row-major (weights). B_KN=true: B stored [K,N].
// EPI: 0 = none, 1 = sigmoid(acc + bias[n]), 2 = sigmoid(acc + bias[n]) * scale[n]
// All dims assumed divisible: M%64==0, N%64==0, K%16==0 (true for every call).
template<int EPI, bool B_KN>
__global__ __launch_bounds__(256)
void gemm64(const float* __restrict__ Ain, size_t offA,
            const float* __restrict__ Bin, size_t offB,
            size_t offC,
            int M, int N, int K,
            const float* __restrict__ bias,
            const float* __restrict__ scale)
{
    const float* A = Ain ? Ain : (g_scratch + offA);
    const float* B = Bin ? Bin : (g_scratch + offB);
    float* C = g_scratch + offC;

    __shared__ float As[16][64];
    __shared__ float Bs[16][64];

    const int tid = threadIdx.x;
    const int tx = tid & 15;   // n-dir (16 threads)
    const int ty = tid >> 4;   // m-dir (16 threads)
    const int m0 = blockIdx.y * 64;
    const int n0 = blockIdx.x * 64;

    float acc[4][4] = {};

    // A tile loader: 64x16 floats, one float4 per thread
    const int la_m = tid >> 2;          // 0..63
    const int la_k = (tid & 3) * 4;     // 0,4,8,12
    const float* Aload = A + (size_t)(m0 + la_m) * K + la_k;

    // B tile loader
    const float* Bload;
    int lb_r, lb_c;
    if (!B_KN) {                         // B is [N,K]
        lb_r = tid >> 2;                 // n: 0..63
        lb_c = (tid & 3) * 4;            // k: 0,4,8,12
        Bload = B + (size_t)(n0 + lb_r) * K + lb_c;
    } else {                             // B is [K,N]
        lb_r = tid >> 4;                 // k: 0..15
        lb_c = (tid & 15) * 4;           // n: 0..60
        Bload = B + (size_t)lb_r * N + n0 + lb_c;
    }

    for (int k0 = 0; k0 < K; k0 += 16) {
        float4 av = *(const float4*)(Aload + k0);
        As[la_k + 0][la_m] = av.x;
        As[la_k + 1][la_m] = av.y;
        As[la_k + 2][la_m] = av.z;
        As[la_k + 3][la_m] = av.w;

        if (!B_KN) {
            float4 bv = *(const float4*)(Bload + k0);
            Bs[lb_c + 0][lb_r] = bv.x;
            Bs[lb_c + 1][lb_r] = bv.y;
            Bs[lb_c + 2][lb_r] = bv.z;
            Bs[lb_c + 3][lb_r] = bv.w;
        } else {
            float4 bv = *(const float4*)(Bload + (size_t)k0 * N);
            *(float4*)&Bs[lb_r][lb_c] = bv;
        }
        __syncthreads();

        #pragma unroll
        for (int kk = 0; kk < 16; kk++) {
            float4 a4 = *(const float4*)&As[kk][ty * 4];
            float4 b4 = *(const float4*)&Bs[kk][tx * 4];
            float ar[4] = {a4.x, a4.y, a4.z, a4.w};
            float br[4] = {b4.x, b4.y, b4.z, b4.w};
            #pragma unroll
            for (int i = 0; i < 4; i++)
                #pragma unroll
                for (int j = 0; j < 4; j++)
                    acc[i][j] += ar[i] * br[j];
        }
        __syncthreads();
    }

    // Epilogue + store (float4 per output row)
    #pragma unroll
    for (int i = 0; i < 4; i++) {
        const int row = m0 + ty * 4 + i;
        float4 o;
        float* ov = (float*)&o;
        #pragma unroll
        for (int j = 0; j < 4; j++) {
            const int col = n0 + tx * 4 + j;
            float v = acc[i][j];
            if (EPI >= 1) v = 1.0f / (1.0f + __expf(-(v + bias[col])));
            if (EPI == 2) v *= scale[col];
            ov[j] = v;
        }
        *(float4*)(C + (size_t)row * N + n0 + tx * 4) = o;
    }
}

// ---------------- softmax over L=256, one warp per row ----------------------
__global__ __launch_bounds__(256)
void softmax256()
{
    float* p = g_scratch + OFF_ATTN;
    const int row = blockIdx.x * 8 + threadIdx.y;
    const int lane = threadIdx.x;
    float* r = p + (size_t)row * LL;

    float v[8];
    float mx = -1e30f;
    #pragma unroll
    for (int j = 0; j < 8; j++) {
        v[j] = r[lane + 32 * j];
        mx = fmaxf(mx, v[j]);
    }
    #pragma unroll
    for (int s = 16; s > 0; s >>= 1)
        mx = fmaxf(mx, __shfl_xor_sync(0xffffffff, mx, s));

    float sum = 0.0f;
    #pragma unroll
    for (int j = 0; j < 8; j++) {
        v[j] = __expf(v[j] - mx);
        sum += v[j];
    }
    #pragma unroll
    for (int s = 16; s > 0; s >>= 1)
        sum += __shfl_xor_sync(0xffffffff, sum, s);

    const float inv = 1.0f / sum;
    #pragma unroll
    for (int j = 0; j < 8; j++)
        r[lane + 32 * j] = v[j] * inv;
}

// ---------------- fusion: sum_s it[b,s,c] * w[b,s,c] ------------------------
// Stage 1: partials over 64-row s-chunks (deterministic, coalesced)
__global__ __launch_bounds__(512)
void fusion_partial()
{
    const float* it = g_scratch + OFF_IT;
    const float* w  = g_scratch + OFF_W;
    float* fpart    = g_scratch + OFF_FP;

    const int b = blockIdx.x, ns = blockIdx.y, c = threadIdx.x;
    size_t base = ((size_t)b * SS + (size_t)ns * 64) * CC + c;
    float acc = 0.0f;
    #pragma unroll 4
    for (int s = 0; s < 64; s++)
        acc += it[base + (size_t)s * CC] * w[base + (size_t)s * CC];
    fpart[((size_t)b * 32 + ns) * CC + c] = acc;
}

// Stage 2: reduce the 32 partials
__global__ __launch_bounds__(512)
void fusion_reduce()
{
    const float* fpart = g_scratch + OFF_FP;
    float* fus         = g_scratch + OFF_FU;
    const int b = blockIdx.x, c = threadIdx.x;
    float acc = 0.0f;
    #pragma unroll
    for (int ns = 0; ns < 32; ns++)
        acc += fpart[((size_t)b * 32 + ns) * CC + c];
    fus[(size_t)b * CC + c] = acc;
}

// ---------------- final: out[b,h] = sum_c fusion[b,c] * Wp[h,c] -------------
__global__ __launch_bounds__(256)
void final_gemm(const float* __restrict__ Wp, float* __restrict__ out)
{
    __shared__ float fs[CC];
    const float* fus = g_scratch + OFF_FU;
    const int b = blockIdx.x;
    const int h = blockIdx.y * 256 + threadIdx.x;

    for (int i = threadIdx.x; i < CC; i += 256)
        fs[i] = fus[(size_t)b * CC + i];
    __syncthreads();

    float acc = 0.0f;
    const float4* wp4 = (const float4*)(Wp + (size_t)h * CC);
    const float4* fs4 = (const float4*)fs;
    #pragma unroll 4
    for (int c4 = 0; c4 < CC / 4; c4++) {
        float4 w = wp4[c4], f = fs4[c4];
        acc += w.x * f.x + w.y * f.y + w.z * f.z + w.w * f.w;
    }
    out[(size_t)b * HH + h] = acc;
}

// ---------------- launch ----------------------------------------------------
extern "C" void kernel_launch(void* const* d_in, const int* in_sizes, int n_in,
                              void* d_out, int out_size)
{
    const float* x   = (const float*)d_in[0];   // [B,S,H]
    const float* lab = (const float*)d_in[1];   // [L,H]
    const float* Wi  = (const float*)d_in[2];   // [C,H]
    const float* bi  = (const float*)d_in[3];   // [C]
    const float* Wl  = (const float*)d_in[4];   // [C,H]
    const float* bl  = (const float*)d_in[5];   // [C]
    const float* Wia = (const float*)d_in[6];   // [C,H]
    const float* bia = (const float*)d_in[7];   // [C]
    const float* Wla = (const float*)d_in[8];   // [C,H]
    const float* bla = (const float*)d_in[9];   // [C]
    const float* ctx = (const float*)d_in[10];  // [C]
    const float* Wp  = (const float*)d_in[11];  // [H,C]
    float* out = (float*)d_out;                 // [B,H] fp32

    // label_trans = sigmoid(lab @ Wl^T + bl)          -> [L,C]
    gemm64<1, false><<<dim3(CC / 64, LL / 64), 256>>>(lab, 0, Wl, 0, OFF_LT,
                                                      LL, CC, HH, bl, nullptr);
    // label_attn = sigmoid(lab @ Wla^T + bla)         -> [L,C]
    gemm64<1, false><<<dim3(CC / 64, LL / 64), 256>>>(lab, 0, Wla, 0, OFF_LA,
                                                      LL, CC, HH, bla, nullptr);
    // input_trans = sigmoid(x @ Wi^T + bi)            -> [M,C]
    gemm64<1, false><<<dim3(CC / 64, MROWS / 64), 256>>>(x, 0, Wi, 0, OFF_IT,
                                                         MROWS, CC, HH, bi, nullptr);
    // input_attn' = sigmoid(x @ Wia^T + bia) * ctx    -> [M,C]
    gemm64<2, false><<<dim3(CC / 64, MROWS / 64), 256>>>(x, 0, Wia, 0, OFF_IA,
                                                         MROWS, CC, HH, bia, ctx);
    // logits = ia' @ la^T                             -> [M,L]
    gemm64<0, false><<<dim3(LL / 64, MROWS / 64), 256>>>(nullptr, OFF_IA, nullptr, OFF_LA,
                                                         OFF_ATTN, MROWS, LL, CC,
                                                         nullptr, nullptr);
    // softmax over L (in place -> attn)
    softmax256<<<MROWS / 8, dim3(32, 8)>>>();
    // weighted = attn @ lt  (lt stored [L,C] = [K,N]) -> [M,C]
    gemm64<0, true><<<dim3(CC / 64, MROWS / 64), 256>>>(nullptr, OFF_ATTN, nullptr, OFF_LT,
                                                        OFF_W, MROWS, CC, LL,
                                                        nullptr, nullptr);
    // fusion[b,c] = sum_s it * weighted
    fusion_partial<<<dim3(BB, 32), 512>>>();
    fusion_reduce<<<BB, 512>>>();
    // out = fusion @ Wp^T
    final_gemm<<<dim3(BB, HH / 256), 256>>>(Wp, out);
}

// round 2
// speedup vs baseline: 1.2150x; 1.2150x over previous
#include <cuda_runtime.h>
#include <cstddef>

// Problem dims (fixed)
#define BB 16
#define SS 2048
#define LL 256
#define HH 768
#define CC 512
#define MROWS (BB*SS)   // 32768

// ---------------- scratch (static device memory; no runtime alloc) ----------
constexpr size_t N_BSC  = (size_t)MROWS * CC;       // 16,777,216
constexpr size_t N_BSL  = (size_t)MROWS * LL;       // 8,388,608
constexpr size_t OFF_IT   = 0;
constexpr size_t OFF_IA   = OFF_IT + N_BSC;
constexpr size_t OFF_W    = OFF_IA + N_BSC;
constexpr size_t OFF_ATTN = OFF_W  + N_BSC;
constexpr size_t OFF_LT   = OFF_ATTN + N_BSL;
constexpr size_t OFF_LA   = OFF_LT + (size_t)LL * CC;
constexpr size_t OFF_FP   = OFF_LA + (size_t)LL * CC;
constexpr size_t OFF_FU   = OFF_FP + (size_t)BB * 32 * CC;
constexpr size_t SCRATCH_ELEMS = OFF_FU + (size_t)BB * CC;

__device__ float g_scratch[SCRATCH_ELEMS];

// ---------------- tiled fp32 GEMM: C[m,n] = op( sum_k A[m,k] * B(n,k) ) -----
// BM=BN=128, BK=16, 256 threads, 8x8 register microtile per thread.
// B_KN=false: B stored [N,K] row-major (weights). B_KN=true: B stored [K,N].
// EPI: 0 = none, 1 = sigmoid(acc + bias[n]), 2 = sigmoid(acc + bias[n]) * scale[n]
// All dims divisible: M%128==0, N%128==0, K%16==0 (true for every call).
template<int EPI, bool B_KN>
__global__ __launch_bounds__(256, 2)
void gemm128(const float* __restrict__ Ain, size_t offA,
             const float* __restrict__ Bin, size_t offB,
             size_t offC,
             int M, int N, int K,
             const float* __restrict__ bias,
             const float* __restrict__ scale)
{
    const float* A = Ain ? Ain : (g_scratch + offA);
    const float* B = Bin ? Bin : (g_scratch + offB);
    float* C = g_scratch + offC;

    __shared__ float As[16][128];
    __shared__ float Bs[16][128];

    const int tid = threadIdx.x;
    const int tx = tid & 15;    // n-dir (16 threads)
    const int ty = tid >> 4;    // m-dir (16 threads)
    const int m0 = blockIdx.y * 128;
    const int n0 = blockIdx.x * 128;

    float acc[8][8] = {};

    // A loader: 128 rows x 16 cols per tile; each thread loads 2 float4
    const int la_r = tid >> 2;          // 0..63
    const int la_c = (tid & 3) * 4;     // 0,4,8,12
    const float* Ap0 = A + (size_t)(m0 + la_r)      * K + la_c;
    const float* Ap1 = A + (size_t)(m0 + la_r + 64) * K + la_c;

    // B loader
    const float* Bp0 = nullptr;
    const float* Bp1 = nullptr;
    int lbk = 0, lbn = 0;
    if (!B_KN) {                        // B is [N,K]
        Bp0 = B + (size_t)(n0 + la_r)      * K + la_c;
        Bp1 = B + (size_t)(n0 + la_r + 64) * K + la_c;
    } else {                            // B is [K,N]
        lbk = tid >> 4;                 // 0..15
        lbn = (tid & 15) * 8;           // 0..120
        Bp0 = B + (size_t)lbk * N + n0 + lbn;
    }

    for (int k0 = 0; k0 < K; k0 += 16) {
        float4 a0 = *(const float4*)(Ap0 + k0);
        float4 a1 = *(const float4*)(Ap1 + k0);
        As[la_c + 0][la_r] = a0.x;
        As[la_c + 1][la_r] = a0.y;
        As[la_c + 2][la_r] = a0.z;
        As[la_c + 3][la_r] = a0.w;
        As[la_c + 0][la_r + 64] = a1.x;
        As[la_c + 1][la_r + 64] = a1.y;
        As[la_c + 2][la_r + 64] = a1.z;
        As[la_c + 3][la_r + 64] = a1.w;

        if (!B_KN) {
            float4 b0 = *(const float4*)(Bp0 + k0);
            float4 b1 = *(const float4*)(Bp1 + k0);
            Bs[la_c + 0][la_r] = b0.x;
            Bs[la_c + 1][la_r] = b0.y;
            Bs[la_c + 2][la_r] = b0.z;
            Bs[la_c + 3][la_r] = b0.w;
            Bs[la_c + 0][la_r + 64] = b1.x;
            Bs[la_c + 1][la_r + 64] = b1.y;
            Bs[la_c + 2][la_r + 64] = b1.z;
            Bs[la_c + 3][la_r + 64] = b1.w;
        } else {
            float4 b0 = *(const float4*)(Bp0 + (size_t)k0 * N);
            float4 b1 = *(const float4*)(Bp0 + (size_t)k0 * N + 4);
            *(float4*)&Bs[lbk][lbn]     = b0;
            *(float4*)&Bs[lbk][lbn + 4] = b1;
        }
        __syncthreads();

        #pragma unroll
        for (int kk = 0; kk < 16; kk++) {
            float ar[8], br[8];
            *(float4*)&ar[0] = *(const float4*)&As[kk][ty * 4];
            *(float4*)&ar[4] = *(const float4*)&As[kk][64 + ty * 4];
            *(float4*)&br[0] = *(const float4*)&Bs[kk][tx * 4];
            *(float4*)&br[4] = *(const float4*)&Bs[kk][64 + tx * 4];
            #pragma unroll
            for (int i = 0; i < 8; i++)
                #pragma unroll
                for (int j = 0; j < 8; j++)
                    acc[i][j] += ar[i] * br[j];
        }
        __syncthreads();
    }

    // Preload bias/scale for this thread's 8 output columns
    float bv[8], sv[8];
    if (EPI >= 1) {
        #pragma unroll
        for (int j = 0; j < 8; j++) {
            const int col = n0 + (j < 4 ? tx * 4 + j : 64 + tx * 4 + j - 4);
            bv[j] = bias[col];
            if (EPI == 2) sv[j] = scale[col];
        }
    }

    // Epilogue + store: 8 rows x (two float4 column groups)
    #pragma unroll
    for (int i = 0; i < 8; i++) {
        const int row = m0 + (i < 4 ? ty * 4 + i : 64 + ty * 4 + i - 4);
        float4 o0, o1;
        float* p0 = (float*)&o0;
        float* p1 = (float*)&o1;
        #pragma unroll
        for (int j = 0; j < 4; j++) {
            float v = acc[i][j];
            if (EPI >= 1) v = 1.0f / (1.0f + __expf(-(v + bv[j])));
            if (EPI == 2) v *= sv[j];
            p0[j] = v;
            float w = acc[i][j + 4];
            if (EPI >= 1) w = 1.0f / (1.0f + __expf(-(w + bv[j + 4])));
            if (EPI == 2) w *= sv[j + 4];
            p1[j] = w;
        }
        *(float4*)(C + (size_t)row * N + n0 + tx * 4)      = o0;
        *(float4*)(C + (size_t)row * N + n0 + 64 + tx * 4) = o1;
    }
}

// ---------------- softmax over L=256, one warp per row ----------------------
__global__ __launch_bounds__(256)
void softmax256()
{
    float* p = g_scratch + OFF_ATTN;
    const int row = blockIdx.x * 8 + threadIdx.y;
    const int lane = threadIdx.x;
    float* r = p + (size_t)row * LL;

    float v[8];
    float mx = -1e30f;
    #pragma unroll
    for (int j = 0; j < 8; j++) {
        v[j] = r[lane + 32 * j];
        mx = fmaxf(mx, v[j]);
    }
    #pragma unroll
    for (int s = 16; s > 0; s >>= 1)
        mx = fmaxf(mx, __shfl_xor_sync(0xffffffff, mx, s));

    float sum = 0.0f;
    #pragma unroll
    for (int j = 0; j < 8; j++) {
        v[j] = __expf(v[j] - mx);
        sum += v[j];
    }
    #pragma unroll
    for (int s = 16; s > 0; s >>= 1)
        sum += __shfl_xor_sync(0xffffffff, sum, s);

    const float inv = 1.0f / sum;
    #pragma unroll
    for (int j = 0; j < 8; j++)
        r[lane + 32 * j] = v[j] * inv;
}

// ---------------- fusion: sum_s it[b,s,c] * w[b,s,c] ------------------------
__global__ __launch_bounds__(512)
void fusion_partial()
{
    const float* it = g_scratch + OFF_IT;
    const float* w  = g_scratch + OFF_W;
    float* fpart    = g_scratch + OFF_FP;

    const int b = blockIdx.x, ns = blockIdx.y, c = threadIdx.x;
    size_t base = ((size_t)b * SS + (size_t)ns * 64) * CC + c;
    float acc = 0.0f;
    #pragma unroll 4
    for (int s = 0; s < 64; s++)
        acc += it[base + (size_t)s * CC] * w[base + (size_t)s * CC];
    fpart[((size_t)b * 32 + ns) * CC + c] = acc;
}

__global__ __launch_bounds__(512)
void fusion_reduce()
{
    const float* fpart = g_scratch + OFF_FP;
    float* fus         = g_scratch + OFF_FU;
    const int b = blockIdx.x, c = threadIdx.x;
    float acc = 0.0f;
    #pragma unroll
    for (int ns = 0; ns < 32; ns++)
        acc += fpart[((size_t)b * 32 + ns) * CC + c];
    fus[(size_t)b * CC + c] = acc;
}

// ---------------- final: out[b,h] = sum_c fusion[b,c] * Wp[h,c] -------------
__global__ __launch_bounds__(256)
void final_gemm(const float* __restrict__ Wp, float* __restrict__ out)
{
    __shared__ float fs[CC];
    const float* fus = g_scratch + OFF_FU;
    const int b = blockIdx.x;
    const int h = blockIdx.y * 256 + threadIdx.x;

    for (int i = threadIdx.x; i < CC; i += 256)
        fs[i] = fus[(size_t)b * CC + i];
    __syncthreads();

    float acc = 0.0f;
    const float4* wp4 = (const float4*)(Wp + (size_t)h * CC);
    const float4* fs4 = (const float4*)fs;
    #pragma unroll 4
    for (int c4 = 0; c4 < CC / 4; c4++) {
        float4 w = wp4[c4], f = fs4[c4];
        acc += w.x * f.x + w.y * f.y + w.z * f.z + w.w * f.w;
    }
    out[(size_t)b * HH + h] = acc;
}

// ---------------- launch ----------------------------------------------------
extern "C" void kernel_launch(void* const* d_in, const int* in_sizes, int n_in,
                              void* d_out, int out_size)
{
    const float* x   = (const float*)d_in[0];   // [B,S,H]
    const float* lab = (const float*)d_in[1];   // [L,H]
    const float* Wi  = (const float*)d_in[2];   // [C,H]
    const float* bi  = (const float*)d_in[3];   // [C]
    const float* Wl  = (const float*)d_in[4];   // [C,H]
    const float* bl  = (const float*)d_in[5];   // [C]
    const float* Wia = (const float*)d_in[6];   // [C,H]
    const float* bia = (const float*)d_in[7];   // [C]
    const float* Wla = (const float*)d_in[8];   // [C,H]
    const float* bla = (const float*)d_in[9];   // [C]
    const float* ctx = (const float*)d_in[10];  // [C]
    const float* Wp  = (const float*)d_in[11];  // [H,C]
    float* out = (float*)d_out;                 // [B,H] fp32

    // label_trans = sigmoid(lab @ Wl^T + bl)          -> [L,C]
    gemm128<1, false><<<dim3(CC / 128, LL / 128), 256>>>(lab, 0, Wl, 0, OFF_LT,
                                                         LL, CC, HH, bl, nullptr);
    // label_attn = sigmoid(lab @ Wla^T + bla)         -> [L,C]
    gemm128<1, false><<<dim3(CC / 128, LL / 128), 256>>>(lab, 0, Wla, 0, OFF_LA,
                                                         LL, CC, HH, bla, nullptr);
    // input_trans = sigmoid(x @ Wi^T + bi)            -> [M,C]
    gemm128<1, false><<<dim3(CC / 128, MROWS / 128), 256>>>(x, 0, Wi, 0, OFF_IT,
                                                            MROWS, CC, HH, bi, nullptr);
    // input_attn' = sigmoid(x @ Wia^T + bia) * ctx    -> [M,C]
    gemm128<2, false><<<dim3(CC / 128, MROWS / 128), 256>>>(x, 0, Wia, 0, OFF_IA,
                                                            MROWS, CC, HH, bia, ctx);
    // logits = ia' @ la^T                             -> [M,L]
    gemm128<0, false><<<dim3(LL / 128, MROWS / 128), 256>>>(nullptr, OFF_IA, nullptr, OFF_LA,
                                                            OFF_ATTN, MROWS, LL, CC,
                                                            nullptr, nullptr);
    // softmax over L (in place -> attn)
    softmax256<<<MROWS / 8, dim3(32, 8)>>>();
    // weighted = attn @ lt  (lt stored [L,C] = [K,N]) -> [M,C]
    gemm128<0, true><<<dim3(CC / 128, MROWS / 128), 256>>>(nullptr, OFF_ATTN, nullptr, OFF_LT,
                                                           OFF_W, MROWS, CC, LL,
                                                           nullptr, nullptr);
    // fusion[b,c] = sum_s it * weighted
    fusion_partial<<<dim3(BB, 32), 512>>>();
    fusion_reduce<<<BB, 512>>>();
    // out = fusion @ Wp^T
    final_gemm<<<dim3(BB, HH / 256), 256>>>(Wp, out);
}

// round 5
// speedup vs baseline: 2.2085x; 1.8176x over previous
#include <cuda_runtime.h>
#include <cuda_bf16.h>
#include <cstdint>
#include <cstddef>

// Problem dims (fixed)
#define BB 16
#define SS 2048
#define LL 256
#define HH 768
#define CC 512
#define MROWS (BB*SS)   // 32768

typedef __nv_bfloat16  bf16;
typedef __nv_bfloat162 bf162;

// ---------------- one static scratch pool, byte-addressed -------------------
constexpr size_t SZ_IT     = (size_t)MROWS * CC * 4;
constexpr size_t SZ_LOGITS = (size_t)MROWS * LL * 4;
constexpr size_t SZ_W      = (size_t)MROWS * CC * 4;
constexpr size_t SZ_FP     = (size_t)BB * 32 * CC * 4;
constexpr size_t SZ_FU     = (size_t)BB * CC * 4;
constexpr size_t SZ_X2     = (size_t)MROWS * HH * 2;
constexpr size_t SZ_LAB2   = (size_t)LL * HH * 2;
constexpr size_t SZ_WT2    = (size_t)CC * HH * 2;
constexpr size_t SZ_IA2    = (size_t)MROWS * CC * 2;
constexpr size_t SZ_ATT2   = (size_t)MROWS * LL * 2;
constexpr size_t SZ_LC2    = (size_t)LL * CC * 2;

constexpr size_t OFF_IT     = 0;
constexpr size_t OFF_LOGITS = OFF_IT + SZ_IT;
constexpr size_t OFF_W      = OFF_LOGITS + SZ_LOGITS;
constexpr size_t OFF_FP     = OFF_W + SZ_W;
constexpr size_t OFF_FU     = OFF_FP + SZ_FP;
constexpr size_t OFF_XH     = OFF_FU + SZ_FU;
constexpr size_t OFF_XL     = OFF_XH + SZ_X2;
constexpr size_t OFF_LABH   = OFF_XL + SZ_X2;
constexpr size_t OFF_LABL   = OFF_LABH + SZ_LAB2;
constexpr size_t OFF_WIH    = OFF_LABL + SZ_LAB2;
constexpr size_t OFF_WIL    = OFF_WIH + SZ_WT2;
constexpr size_t OFF_WLH    = OFF_WIL + SZ_WT2;
constexpr size_t OFF_WLL    = OFF_WLH + SZ_WT2;
constexpr size_t OFF_WIAH   = OFF_WLL + SZ_WT2;
constexpr size_t OFF_WIAL   = OFF_WIAH + SZ_WT2;
constexpr size_t OFF_WLAH   = OFF_WIAL + SZ_WT2;
constexpr size_t OFF_WLAL   = OFF_WLAH + SZ_WT2;
constexpr size_t OFF_IAH    = OFF_WLAL + SZ_WT2;
constexpr size_t OFF_IAL    = OFF_IAH + SZ_IA2;
constexpr size_t OFF_ATTH   = OFF_IAL + SZ_IA2;
constexpr size_t OFF_ATTL   = OFF_ATTH + SZ_ATT2;
constexpr size_t OFF_LTH    = OFF_ATTL + SZ_ATT2;
constexpr size_t OFF_LTL    = OFF_LTH + SZ_LC2;
constexpr size_t OFF_LAH    = OFF_LTL + SZ_LC2;
constexpr size_t OFF_LAL    = OFF_LAH + SZ_LC2;
constexpr size_t POOL_BYTES = OFF_LAL + SZ_LC2;

__device__ __align__(16) unsigned char g_pool[POOL_BYTES];

// ---------------- helpers ---------------------------------------------------
__device__ __forceinline__ uint32_t smem_u32(const void* p) {
    uint32_t a;
    asm("{ .reg .u64 t; cvta.to.shared.u64 t, %1; cvt.u32.u64 %0, t; }" : "=r"(a) : "l"(p));
    return a;
}
__device__ __forceinline__ void cp16(uint32_t dst, const void* src) {
    asm volatile("cp.async.cg.shared.global [%0], [%1], 16;" :: "r"(dst), "l"(src) : "memory");
}
#define CP_COMMIT() asm volatile("cp.async.commit_group;" ::: "memory")
#define CP_WAIT0()  asm volatile("cp.async.wait_group 0;"  ::: "memory")

#define LDSM4(R0,R1,R2,R3,ADDR) \
    asm volatile("ldmatrix.sync.aligned.m8n8.x4.shared.b16 {%0,%1,%2,%3}, [%4];" \
                 : "=r"(R0),"=r"(R1),"=r"(R2),"=r"(R3) : "r"(ADDR))

#define MMA_BF16(C,A,B) \
    asm volatile("mma.sync.aligned.m16n8k16.row.col.f32.bf16.bf16.f32 " \
                 "{%0,%1,%2,%3},{%4,%5,%6,%7},{%8,%9},{%0,%1,%2,%3};" \
                 : "+f"((C)[0]),"+f"((C)[1]),"+f"((C)[2]),"+f"((C)[3]) \
                 : "r"((A)[0]),"r"((A)[1]),"r"((A)[2]),"r"((A)[3]), \
                   "r"((B)[0]),"r"((B)[1]))

__device__ __forceinline__ void bsplit(float v, bf16& h, bf16& l) {
    h = __float2bfloat16(v);
    l = __float2bfloat16(v - __bfloat162float(h));
}
__device__ __forceinline__ float sigmoidf_(float v) {
    return 1.0f / (1.0f + __expf(-v));
}

// ---------------- fp32 -> bf16 hi/lo split ----------------------------------
__global__ __launch_bounds__(256)
void ksplit(const float4* __restrict__ src, size_t oHi, size_t oLo, int n4)
{
    int i = blockIdx.x * 256 + threadIdx.x;
    if (i >= n4) return;
    bf162* hi = (bf162*)(g_pool + oHi);
    bf162* lo = (bf162*)(g_pool + oLo);
    float4 v = src[i];
    bf16 h0, l0, h1, l1, h2, l2, h3, l3;
    bsplit(v.x, h0, l0); bsplit(v.y, h1, l1);
    bsplit(v.z, h2, l2); bsplit(v.w, h3, l3);
    hi[i * 2 + 0] = __halves2bfloat162(h0, h1);
    hi[i * 2 + 1] = __halves2bfloat162(h2, h3);
    lo[i * 2 + 0] = __halves2bfloat162(l0, l1);
    lo[i * 2 + 1] = __halves2bfloat162(l2, l3);
}

// ---------------- bf16-split mma GEMM ---------------------------------------
// C[M,N] = epi( A @ B^T ), A=[M,K] hi/lo bf16, B=[N,K] hi/lo bf16 (all in pool)
// Block 128x128, BK=32, 256 threads, warps 4(m) x 2(n), warp tile 32x64.
#define SROW  80            // smem bytes per 32-bf16 row (64B data + 16B pad)
#define TILEB (128 * SROW)  // 10240
#define STAGEB (4 * TILEB)  // A_hi, A_lo, B_hi, B_lo
#define GSMEM (2 * STAGEB)  // 81920

enum { EPI_NONE = 0, EPI_SIGC = 1, EPI_SIGC_SCALE = 2, EPI_SIGR = 3 };

template<int EPI, bool OUT_SPLIT>
__global__ __launch_bounds__(256, 1)
void mma_gemm(size_t oAh, size_t oAl, size_t oBh, size_t oBl,
              size_t oCf, size_t oCh, size_t oCl,
              int M, int N, int K,
              const float* __restrict__ bias, const float* __restrict__ scale)
{
    const bf16* Ah = (const bf16*)(g_pool + oAh);
    const bf16* Al = (const bf16*)(g_pool + oAl);
    const bf16* Bh = (const bf16*)(g_pool + oBh);
    const bf16* Bl = (const bf16*)(g_pool + oBl);
    float* Cf = (float*)(g_pool + oCf);
    bf16* Ch  = (bf16*)(g_pool + oCh);
    bf16* Cl  = (bf16*)(g_pool + oCl);

    extern __shared__ char smem[];
    const uint32_t sb = smem_u32(smem);
    const int tid  = threadIdx.x;
    const int lane = tid & 31;
    const int wid  = tid >> 5;
    const int wm   = wid & 3;       // m offset *32
    const int wn   = wid >> 2;      // n offset *64
    const int m0 = blockIdx.y * 128;
    const int n0 = blockIdx.x * 128;

    // loader: 2 threads per 32-elem row, each covers 16 bf16 (32B)
    const int lr = tid >> 1;
    const int lh = tid & 1;
    const bf16* gAh = Ah + (size_t)(m0 + lr) * K + lh * 16;
    const bf16* gAl = Al + (size_t)(m0 + lr) * K + lh * 16;
    const bf16* gBh = Bh + (size_t)(n0 + lr) * K + lh * 16;
    const bf16* gBl = Bl + (size_t)(n0 + lr) * K + lh * 16;
    const uint32_t sdst = (uint32_t)(lr * SROW + lh * 32);

    const int NCH = K / 32;
    float c[2][8][4] = {};

    {
        uint32_t d = sb + sdst;
        cp16(d,              gAh);     cp16(d + 16,              gAh + 8);
        cp16(d + TILEB,      gAl);     cp16(d + TILEB + 16,      gAl + 8);
        cp16(d + 2 * TILEB,  gBh);     cp16(d + 2 * TILEB + 16,  gBh + 8);
        cp16(d + 3 * TILEB,  gBl);     cp16(d + 3 * TILEB + 16,  gBl + 8);
        CP_COMMIT();
        CP_WAIT0();
        __syncthreads();
    }

    for (int ch = 0; ch < NCH; ch++) {
        if (ch + 1 < NCH) {
            const int k0 = (ch + 1) * 32;
            uint32_t d = sb + ((ch + 1) & 1) * STAGEB + sdst;
            cp16(d,             gAh + k0);     cp16(d + 16,             gAh + k0 + 8);
            cp16(d + TILEB,     gAl + k0);     cp16(d + TILEB + 16,     gAl + k0 + 8);
            cp16(d + 2 * TILEB, gBh + k0);     cp16(d + 2 * TILEB + 16, gBh + k0 + 8);
            cp16(d + 3 * TILEB, gBl + k0);     cp16(d + 3 * TILEB + 16, gBl + k0 + 8);
            CP_COMMIT();
        }

        const uint32_t base = sb + (ch & 1) * STAGEB;
        #pragma unroll
        for (int ks = 0; ks < 2; ks++) {
            uint32_t ah[2][4], al[2][4];
            #pragma unroll
            for (int mf = 0; mf < 2; mf++) {
                uint32_t addr = base
                    + (uint32_t)((wm * 32 + mf * 16 + (lane & 15)) * SROW)
                    + (uint32_t)(ks * 32 + (lane >> 4) * 16);
                LDSM4(ah[mf][0], ah[mf][1], ah[mf][2], ah[mf][3], addr);
                LDSM4(al[mf][0], al[mf][1], al[mf][2], al[mf][3], addr + TILEB);
            }
            uint32_t bh[8][2], bl[8][2];
            const int g = lane >> 3;
            #pragma unroll
            for (int p = 0; p < 4; p++) {
                uint32_t addr = base + 2 * TILEB
                    + (uint32_t)((wn * 64 + p * 16 + ((g & 2) ? 8 : 0) + (lane & 7)) * SROW)
                    + (uint32_t)(ks * 32 + (g & 1) * 16);
                uint32_t r0, r1, r2, r3;
                LDSM4(r0, r1, r2, r3, addr);
                bh[2 * p][0] = r0; bh[2 * p][1] = r1;
                bh[2 * p + 1][0] = r2; bh[2 * p + 1][1] = r3;
                LDSM4(r0, r1, r2, r3, addr + TILEB);
                bl[2 * p][0] = r0; bl[2 * p][1] = r1;
                bl[2 * p + 1][0] = r2; bl[2 * p + 1][1] = r3;
            }
            #pragma unroll
            for (int mf = 0; mf < 2; mf++)
                #pragma unroll
                for (int nf = 0; nf < 8; nf++) {
                    MMA_BF16(c[mf][nf], ah[mf], bh[nf]);
                    MMA_BF16(c[mf][nf], ah[mf], bl[nf]);
                    MMA_BF16(c[mf][nf], al[mf], bh[nf]);
                }
        }
        if (ch + 1 < NCH) CP_WAIT0();
        __syncthreads();
    }

    const int quad = lane >> 2;
    const int tq   = lane & 3;
    #pragma unroll
    for (int mf = 0; mf < 2; mf++) {
        const int r0 = m0 + wm * 32 + mf * 16 + quad;
        const int r1 = r0 + 8;
        float rb0 = 0.f, rb1 = 0.f;
        if (EPI == EPI_SIGR) { rb0 = bias[r0]; rb1 = bias[r1]; }
        #pragma unroll
        for (int nf = 0; nf < 8; nf++) {
            const int col = n0 + wn * 64 + nf * 8 + tq * 2;
            float v0 = c[mf][nf][0], v1 = c[mf][nf][1];
            float v2 = c[mf][nf][2], v3 = c[mf][nf][3];
            if (EPI == EPI_SIGC || EPI == EPI_SIGC_SCALE) {
                float2 bb = *(const float2*)(bias + col);
                v0 = sigmoidf_(v0 + bb.x); v1 = sigmoidf_(v1 + bb.y);
                v2 = sigmoidf_(v2 + bb.x); v3 = sigmoidf_(v3 + bb.y);
            } else if (EPI == EPI_SIGR) {
                v0 = sigmoidf_(v0 + rb0); v1 = sigmoidf_(v1 + rb0);
                v2 = sigmoidf_(v2 + rb1); v3 = sigmoidf_(v3 + rb1);
            }
            if (EPI == EPI_SIGC_SCALE) {
                float2 ss = *(const float2*)(scale + col);
                v0 *= ss.x; v1 *= ss.y; v2 *= ss.x; v3 *= ss.y;
            }
            if (OUT_SPLIT) {
                bf16 h0, l0, h1, l1;
                bsplit(v0, h0, l0); bsplit(v1, h1, l1);
                *(bf162*)(Ch + (size_t)r0 * N + col) = __halves2bfloat162(h0, h1);
                *(bf162*)(Cl + (size_t)r0 * N + col) = __halves2bfloat162(l0, l1);
                bsplit(v2, h0, l0); bsplit(v3, h1, l1);
                *(bf162*)(Ch + (size_t)r1 * N + col) = __halves2bfloat162(h0, h1);
                *(bf162*)(Cl + (size_t)r1 * N + col) = __halves2bfloat162(l0, l1);
            } else {
                *(float2*)(Cf + (size_t)r0 * N + col) = make_float2(v0, v1);
                *(float2*)(Cf + (size_t)r1 * N + col) = make_float2(v2, v3);
            }
        }
    }
}

// ---------------- softmax over L=256; writes bf16-split attn ----------------
__global__ __launch_bounds__(256)
void softmax256()
{
    const float* logits = (const float*)(g_pool + OFF_LOGITS);
    bf16* atth = (bf16*)(g_pool + OFF_ATTH);
    bf16* attl = (bf16*)(g_pool + OFF_ATTL);

    const int row = blockIdx.x * 8 + threadIdx.y;
    const int lane = threadIdx.x;
    const float* r = logits + (size_t)row * LL;

    float v[8];
    float mx = -1e30f;
    #pragma unroll
    for (int j = 0; j < 8; j++) {
        v[j] = r[lane + 32 * j];
        mx = fmaxf(mx, v[j]);
    }
    #pragma unroll
    for (int s = 16; s > 0; s >>= 1)
        mx = fmaxf(mx, __shfl_xor_sync(0xffffffff, mx, s));

    float sum = 0.0f;
    #pragma unroll
    for (int j = 0; j < 8; j++) {
        v[j] = __expf(v[j] - mx);
        sum += v[j];
    }
    #pragma unroll
    for (int s = 16; s > 0; s >>= 1)
        sum += __shfl_xor_sync(0xffffffff, sum, s);

    const float inv = 1.0f / sum;
    const size_t ro = (size_t)row * LL;
    #pragma unroll
    for (int j = 0; j < 8; j++) {
        float p = v[j] * inv;
        bf16 h, l;
        bsplit(p, h, l);
        atth[ro + lane + 32 * j] = h;
        attl[ro + lane + 32 * j] = l;
    }
}

// ---------------- fusion: sum_s it[b,s,c] * w[b,s,c] ------------------------
__global__ __launch_bounds__(512)
void fusion_partial()
{
    const float* it = (const float*)(g_pool + OFF_IT);
    const float* w  = (const float*)(g_pool + OFF_W);
    float* fp = (float*)(g_pool + OFF_FP);

    const int b = blockIdx.x, ns = blockIdx.y, cidx = threadIdx.x;
    size_t base = ((size_t)b * SS + (size_t)ns * 64) * CC + cidx;
    float acc = 0.0f;
    #pragma unroll 4
    for (int s = 0; s < 64; s++)
        acc += it[base + (size_t)s * CC] * w[base + (size_t)s * CC];
    fp[((size_t)b * 32 + ns) * CC + cidx] = acc;
}

__global__ __launch_bounds__(512)
void fusion_reduce()
{
    const float* fp = (const float*)(g_pool + OFF_FP);
    float* fu = (float*)(g_pool + OFF_FU);
    const int b = blockIdx.x, cidx = threadIdx.x;
    float acc = 0.0f;
    #pragma unroll
    for (int ns = 0; ns < 32; ns++)
        acc += fp[((size_t)b * 32 + ns) * CC + cidx];
    fu[(size_t)b * CC + cidx] = acc;
}

// ---------------- final: out[b,h] = sum_c fusion[b,c] * Wp[h,c] -------------
__global__ __launch_bounds__(256)
void final_gemm(const float* __restrict__ Wp, float* __restrict__ out)
{
    __shared__ float fs[CC];
    const float* fu = (const float*)(g_pool + OFF_FU);
    const int b = blockIdx.x;
    const int h = blockIdx.y * 256 + threadIdx.x;

    for (int i = threadIdx.x; i < CC; i += 256)
        fs[i] = fu[(size_t)b * CC + i];
    __syncthreads();

    float acc = 0.0f;
    const float4* wp4 = (const float4*)(Wp + (size_t)h * CC);
    const float4* fs4 = (const float4*)fs;
    #pragma unroll 4
    for (int c4 = 0; c4 < CC / 4; c4++) {
        float4 w = wp4[c4], f = fs4[c4];
        acc += w.x * f.x + w.y * f.y + w.z * f.z + w.w * f.w;
    }
    out[(size_t)b * HH + h] = acc;
}

// ---------------- launch ----------------------------------------------------
extern "C" void kernel_launch(void* const* d_in, const int* in_sizes, int n_in,
                              void* d_out, int out_size)
{
    const float* x   = (const float*)d_in[0];
    const float* lab = (const float*)d_in[1];
    const float* Wi  = (const float*)d_in[2];
    const float* bi  = (const float*)d_in[3];
    const float* Wl  = (const float*)d_in[4];
    const float* bl  = (const float*)d_in[5];
    const float* Wia = (const float*)d_in[6];
    const float* bia = (const float*)d_in[7];
    const float* Wla = (const float*)d_in[8];
    const float* bla = (const float*)d_in[9];
    const float* ctx = (const float*)d_in[10];
    const float* Wp  = (const float*)d_in[11];
    float* out = (float*)d_out;

    cudaFuncSetAttribute(mma_gemm<EPI_SIGR, true>,        cudaFuncAttributeMaxDynamicSharedMemorySize, GSMEM);
    cudaFuncSetAttribute(mma_gemm<EPI_SIGC, true>,        cudaFuncAttributeMaxDynamicSharedMemorySize, GSMEM);
    cudaFuncSetAttribute(mma_gemm<EPI_SIGC, false>,       cudaFuncAttributeMaxDynamicSharedMemorySize, GSMEM);
    cudaFuncSetAttribute(mma_gemm<EPI_SIGC_SCALE, true>,  cudaFuncAttributeMaxDynamicSharedMemorySize, GSMEM);
    cudaFuncSetAttribute(mma_gemm<EPI_NONE, false>,       cudaFuncAttributeMaxDynamicSharedMemorySize, GSMEM);

    // ---- input splits ----
    ksplit<<<(MROWS * HH / 4 + 255) / 256, 256>>>((const float4*)x,   OFF_XH,   OFF_XL,   MROWS * HH / 4);
    ksplit<<<(LL * HH / 4 + 255) / 256, 256>>>((const float4*)lab, OFF_LABH, OFF_LABL, LL * HH / 4);
    ksplit<<<(CC * HH / 4 + 255) / 256, 256>>>((const float4*)Wi,  OFF_WIH,  OFF_WIL,  CC * HH / 4);
    ksplit<<<(CC * HH / 4 + 255) / 256, 256>>>((const float4*)Wl,  OFF_WLH,  OFF_WLL,  CC * HH / 4);
    ksplit<<<(CC * HH / 4 + 255) / 256, 256>>>((const float4*)Wia, OFF_WIAH, OFF_WIAL, CC * HH / 4);
    ksplit<<<(CC * HH / 4 + 255) / 256, 256>>>((const float4*)Wla, OFF_WLAH, OFF_WLAL, CC * HH / 4);

    // ---- G1: ltT[c,l] = sigmoid(Wl @ lab^T + bl[row])  [512,256], K=768 ----
    mma_gemm<EPI_SIGR, true><<<dim3(LL / 128, CC / 128), 256, GSMEM>>>(
        OFF_WLH, OFF_WLL, OFF_LABH, OFF_LABL, 0, OFF_LTH, OFF_LTL, CC, LL, HH, bl, nullptr);

    // ---- G2: la[l,c] = sigmoid(lab @ Wla^T + bla[col]) [256,512], K=768 ----
    mma_gemm<EPI_SIGC, true><<<dim3(CC / 128, LL / 128), 256, GSMEM>>>(
        OFF_LABH, OFF_LABL, OFF_WLAH, OFF_WLAL, 0, OFF_LAH, OFF_LAL, LL, CC, HH, bla, nullptr);

    // ---- G3: it = sigmoid(x @ Wi^T + bi)  fp32 [32768,512], K=768 ----
    mma_gemm<EPI_SIGC, false><<<dim3(CC / 128, MROWS / 128), 256, GSMEM>>>(
        OFF_XH, OFF_XL, OFF_WIH, OFF_WIL, OFF_IT, 0, 0, MROWS, CC, HH, bi, nullptr);

    // ---- G4: ia' = sigmoid(x @ Wia^T + bia) * ctx  split [32768,512], K=768 ----
    mma_gemm<EPI_SIGC_SCALE, true><<<dim3(CC / 128, MROWS / 128), 256, GSMEM>>>(
        OFF_XH, OFF_XL, OFF_WIAH, OFF_WIAL, 0, OFF_IAH, OFF_IAL, MROWS, CC, HH, bia, ctx);

    // ---- G5: logits = ia' @ la^T  fp32 [32768,256], K=512 ----
    mma_gemm<EPI_NONE, false><<<dim3(LL / 128, MROWS / 128), 256, GSMEM>>>(
        OFF_IAH, OFF_IAL, OFF_LAH, OFF_LAL, OFF_LOGITS, 0, 0, MROWS, LL, CC, nullptr, nullptr);

    // ---- softmax -> attn split ----
    softmax256<<<MROWS / 8, dim3(32, 8)>>>();

    // ---- G7: weighted = attn @ ltT^T  fp32 [32768,512], K=256 ----
    mma_gemm<EPI_NONE, false><<<dim3(CC / 128, MROWS / 128), 256, GSMEM>>>(
        OFF_ATTH, OFF_ATTL, OFF_LTH, OFF_LTL, OFF_W, 0, 0, MROWS, CC, LL, nullptr, nullptr);

    // ---- fusion + final projection ----
    fusion_partial<<<dim3(BB, 32), 512>>>();
    fusion_reduce<<<BB, 512>>>();
    final_gemm<<<dim3(BB, HH / 256), 256>>>(Wp, out);
}

// round 6
// speedup vs baseline: 2.5809x; 1.1686x over previous
#include <cuda_runtime.h>
#include <cuda_bf16.h>
#include <cstdint>
#include <cstddef>

// Problem dims (fixed)
#define BB 16
#define SS 2048
#define LL 256
#define HH 768
#define CC 512
#define MROWS (BB*SS)   // 32768

typedef __nv_bfloat16  bf16;
typedef __nv_bfloat162 bf162;

// ---------------- one static scratch pool, byte-addressed -------------------
constexpr size_t SZ_IT     = (size_t)MROWS * CC * 4;
constexpr size_t SZ_LOGITS = (size_t)MROWS * LL * 4;
constexpr size_t SZ_W      = (size_t)MROWS * CC * 4;
constexpr size_t SZ_FP     = (size_t)BB * 32 * CC * 4;
constexpr size_t SZ_FU     = (size_t)BB * CC * 4;
constexpr size_t SZ_X2     = (size_t)MROWS * HH * 2;
constexpr size_t SZ_LAB2   = (size_t)LL * HH * 2;
constexpr size_t SZ_WT2    = (size_t)CC * HH * 2;
constexpr size_t SZ_IA2    = (size_t)MROWS * CC * 2;
constexpr size_t SZ_ATT2   = (size_t)MROWS * LL * 2;
constexpr size_t SZ_LC2    = (size_t)LL * CC * 2;

constexpr size_t OFF_IT     = 0;
constexpr size_t OFF_LOGITS = OFF_IT + SZ_IT;
constexpr size_t OFF_W      = OFF_LOGITS + SZ_LOGITS;
constexpr size_t OFF_FP     = OFF_W + SZ_W;
constexpr size_t OFF_FU     = OFF_FP + SZ_FP;
constexpr size_t OFF_XH     = OFF_FU + SZ_FU;
constexpr size_t OFF_XL     = OFF_XH + SZ_X2;
constexpr size_t OFF_LABH   = OFF_XL + SZ_X2;
constexpr size_t OFF_LABL   = OFF_LABH + SZ_LAB2;
constexpr size_t OFF_WIH    = OFF_LABL + SZ_LAB2;
constexpr size_t OFF_WIL    = OFF_WIH + SZ_WT2;
constexpr size_t OFF_WLH    = OFF_WIL + SZ_WT2;
constexpr size_t OFF_WLL    = OFF_WLH + SZ_WT2;
constexpr size_t OFF_WIAH   = OFF_WLL + SZ_WT2;
constexpr size_t OFF_WIAL   = OFF_WIAH + SZ_WT2;
constexpr size_t OFF_WLAH   = OFF_WIAL + SZ_WT2;
constexpr size_t OFF_WLAL   = OFF_WLAH + SZ_WT2;
constexpr size_t OFF_IAH    = OFF_WLAL + SZ_WT2;
constexpr size_t OFF_IAL    = OFF_IAH + SZ_IA2;
constexpr size_t OFF_ATTH   = OFF_IAL + SZ_IA2;
constexpr size_t OFF_ATTL   = OFF_ATTH + SZ_ATT2;
constexpr size_t OFF_LTH    = OFF_ATTL + SZ_ATT2;
constexpr size_t OFF_LTL    = OFF_LTH + SZ_LC2;
constexpr size_t OFF_LAH    = OFF_LTL + SZ_LC2;
constexpr size_t OFF_LAL    = OFF_LAH + SZ_LC2;
constexpr size_t POOL_BYTES = OFF_LAL + SZ_LC2;

__device__ __align__(16) unsigned char g_pool[POOL_BYTES];

// ---------------- helpers ---------------------------------------------------
__device__ __forceinline__ uint32_t smem_u32(const void* p) {
    uint32_t a;
    asm("{ .reg .u64 t; cvta.to.shared.u64 t, %1; cvt.u32.u64 %0, t; }" : "=r"(a) : "l"(p));
    return a;
}
__device__ __forceinline__ void cp16(uint32_t dst, const void* src) {
    asm volatile("cp.async.cg.shared.global [%0], [%1], 16;" :: "r"(dst), "l"(src) : "memory");
}
#define CP_COMMIT() asm volatile("cp.async.commit_group;" ::: "memory")
#define CP_WAIT0()  asm volatile("cp.async.wait_group 0;"  ::: "memory")

#define LDSM4(R0,R1,R2,R3,ADDR) \
    asm volatile("ldmatrix.sync.aligned.m8n8.x4.shared.b16 {%0,%1,%2,%3}, [%4];" \
                 : "=r"(R0),"=r"(R1),"=r"(R2),"=r"(R3) : "r"(ADDR))

#define MMA_BF16(C,A,B) \
    asm volatile("mma.sync.aligned.m16n8k16.row.col.f32.bf16.bf16.f32 " \
                 "{%0,%1,%2,%3},{%4,%5,%6,%7},{%8,%9},{%0,%1,%2,%3};" \
                 : "+f"((C)[0]),"+f"((C)[1]),"+f"((C)[2]),"+f"((C)[3]) \
                 : "r"((A)[0]),"r"((A)[1]),"r"((A)[2]),"r"((A)[3]), \
                   "r"((B)[0]),"r"((B)[1]))

__device__ __forceinline__ void bsplit(float v, bf16& h, bf16& l) {
    h = __float2bfloat16(v);
    l = __float2bfloat16(v - __bfloat162float(h));
}
__device__ __forceinline__ float sigmoidf_(float v) {
    return 1.0f / (1.0f + __expf(-v));
}

// ---------------- fp32 -> bf16 hi/lo split ----------------------------------
__global__ __launch_bounds__(256)
void ksplit(const float4* __restrict__ src, size_t oHi, size_t oLo, int n4)
{
    int i = blockIdx.x * 256 + threadIdx.x;
    if (i >= n4) return;
    bf162* hi = (bf162*)(g_pool + oHi);
    bf162* lo = (bf162*)(g_pool + oLo);
    float4 v = src[i];
    bf16 h0, l0, h1, l1, h2, l2, h3, l3;
    bsplit(v.x, h0, l0); bsplit(v.y, h1, l1);
    bsplit(v.z, h2, l2); bsplit(v.w, h3, l3);
    hi[i * 2 + 0] = __halves2bfloat162(h0, h1);
    hi[i * 2 + 1] = __halves2bfloat162(h2, h3);
    lo[i * 2 + 0] = __halves2bfloat162(l0, l1);
    lo[i * 2 + 1] = __halves2bfloat162(l2, l3);
}

// ---------------- bf16-split mma GEMM ---------------------------------------
// C[M,N] = epi( A @ B^T ), A=[M,K] hi/lo bf16, B=[N,K] hi/lo bf16 (all in pool)
// Block 128x128, BK=32, 256 threads, warps 4(m) x 2(n), warp tile 32x64.
#define SROW  80            // smem bytes per 32-bf16 row (64B data + 16B pad)
#define TILEB (128 * SROW)  // 10240
#define STAGEB (4 * TILEB)  // A_hi, A_lo, B_hi, B_lo
#define GSMEM (2 * STAGEB)  // 81920

enum { EPI_NONE = 0, EPI_SIGC = 1, EPI_SIGC_SCALE = 2, EPI_SIGR = 3 };

template<int EPI, bool OUT_SPLIT>
__global__ __launch_bounds__(256, 2)
void mma_gemm(size_t oAh, size_t oAl, size_t oBh, size_t oBl,
              size_t oCf, size_t oCh, size_t oCl,
              int M, int N, int K,
              const float* __restrict__ bias, const float* __restrict__ scale)
{
    const bf16* Ah = (const bf16*)(g_pool + oAh);
    const bf16* Al = (const bf16*)(g_pool + oAl);
    const bf16* Bh = (const bf16*)(g_pool + oBh);
    const bf16* Bl = (const bf16*)(g_pool + oBl);
    float* Cf = (float*)(g_pool + oCf);
    bf16* Ch  = (bf16*)(g_pool + oCh);
    bf16* Cl  = (bf16*)(g_pool + oCl);

    extern __shared__ char smem[];
    const uint32_t sb = smem_u32(smem);
    const int tid  = threadIdx.x;
    const int lane = tid & 31;
    const int wid  = tid >> 5;
    const int wm   = wid & 3;       // m offset *32
    const int wn   = wid >> 2;      // n offset *64
    const int m0 = blockIdx.y * 128;
    const int n0 = blockIdx.x * 128;

    // loader: 2 threads per 32-elem row, each covers 16 bf16 (32B)
    const int lr = tid >> 1;
    const int lh = tid & 1;
    const bf16* gAh = Ah + (size_t)(m0 + lr) * K + lh * 16;
    const bf16* gAl = Al + (size_t)(m0 + lr) * K + lh * 16;
    const bf16* gBh = Bh + (size_t)(n0 + lr) * K + lh * 16;
    const bf16* gBl = Bl + (size_t)(n0 + lr) * K + lh * 16;
    const uint32_t sdst = (uint32_t)(lr * SROW + lh * 32);

    const int NCH = K / 32;
    float c[2][8][4] = {};

    {
        uint32_t d = sb + sdst;
        cp16(d,              gAh);     cp16(d + 16,              gAh + 8);
        cp16(d + TILEB,      gAl);     cp16(d + TILEB + 16,      gAl + 8);
        cp16(d + 2 * TILEB,  gBh);     cp16(d + 2 * TILEB + 16,  gBh + 8);
        cp16(d + 3 * TILEB,  gBl);     cp16(d + 3 * TILEB + 16,  gBl + 8);
        CP_COMMIT();
        CP_WAIT0();
        __syncthreads();
    }

    for (int ch = 0; ch < NCH; ch++) {
        if (ch + 1 < NCH) {
            const int k0 = (ch + 1) * 32;
            uint32_t d = sb + ((ch + 1) & 1) * STAGEB + sdst;
            cp16(d,             gAh + k0);     cp16(d + 16,             gAh + k0 + 8);
            cp16(d + TILEB,     gAl + k0);     cp16(d + TILEB + 16,     gAl + k0 + 8);
            cp16(d + 2 * TILEB, gBh + k0);     cp16(d + 2 * TILEB + 16, gBh + k0 + 8);
            cp16(d + 3 * TILEB, gBl + k0);     cp16(d + 3 * TILEB + 16, gBl + k0 + 8);
            CP_COMMIT();
        }

        const uint32_t base = sb + (ch & 1) * STAGEB;
        #pragma unroll
        for (int ks = 0; ks < 2; ks++) {
            uint32_t ah[2][4], al[2][4];
            #pragma unroll
            for (int mf = 0; mf < 2; mf++) {
                uint32_t addr = base
                    + (uint32_t)((wm * 32 + mf * 16 + (lane & 15)) * SROW)
                    + (uint32_t)(ks * 32 + (lane >> 4) * 16);
                LDSM4(ah[mf][0], ah[mf][1], ah[mf][2], ah[mf][3], addr);
                LDSM4(al[mf][0], al[mf][1], al[mf][2], al[mf][3], addr + TILEB);
            }
            uint32_t bh[8][2], bl[8][2];
            const int g = lane >> 3;
            #pragma unroll
            for (int p = 0; p < 4; p++) {
                uint32_t addr = base + 2 * TILEB
                    + (uint32_t)((wn * 64 + p * 16 + ((g & 2) ? 8 : 0) + (lane & 7)) * SROW)
                    + (uint32_t)(ks * 32 + (g & 1) * 16);
                uint32_t r0, r1, r2, r3;
                LDSM4(r0, r1, r2, r3, addr);
                bh[2 * p][0] = r0; bh[2 * p][1] = r1;
                bh[2 * p + 1][0] = r2; bh[2 * p + 1][1] = r3;
                LDSM4(r0, r1, r2, r3, addr + TILEB);
                bl[2 * p][0] = r0; bl[2 * p][1] = r1;
                bl[2 * p + 1][0] = r2; bl[2 * p + 1][1] = r3;
            }
            #pragma unroll
            for (int mf = 0; mf < 2; mf++)
                #pragma unroll
                for (int nf = 0; nf < 8; nf++) {
                    MMA_BF16(c[mf][nf], ah[mf], bh[nf]);
                    MMA_BF16(c[mf][nf], ah[mf], bl[nf]);
                    MMA_BF16(c[mf][nf], al[mf], bh[nf]);
                }
        }
        if (ch + 1 < NCH) CP_WAIT0();
        __syncthreads();
    }

    const int quad = lane >> 2;
    const int tq   = lane & 3;
    #pragma unroll
    for (int mf = 0; mf < 2; mf++) {
        const int r0 = m0 + wm * 32 + mf * 16 + quad;
        const int r1 = r0 + 8;
        float rb0 = 0.f, rb1 = 0.f;
        if (EPI == EPI_SIGR) { rb0 = bias[r0]; rb1 = bias[r1]; }
        #pragma unroll
        for (int nf = 0; nf < 8; nf++) {
            const int col = n0 + wn * 64 + nf * 8 + tq * 2;
            float v0 = c[mf][nf][0], v1 = c[mf][nf][1];
            float v2 = c[mf][nf][2], v3 = c[mf][nf][3];
            if (EPI == EPI_SIGC || EPI == EPI_SIGC_SCALE) {
                float2 bb = *(const float2*)(bias + col);
                v0 = sigmoidf_(v0 + bb.x); v1 = sigmoidf_(v1 + bb.y);
                v2 = sigmoidf_(v2 + bb.x); v3 = sigmoidf_(v3 + bb.y);
            } else if (EPI == EPI_SIGR) {
                v0 = sigmoidf_(v0 + rb0); v1 = sigmoidf_(v1 + rb0);
                v2 = sigmoidf_(v2 + rb1); v3 = sigmoidf_(v3 + rb1);
            }
            if (EPI == EPI_SIGC_SCALE) {
                float2 ss = *(const float2*)(scale + col);
                v0 *= ss.x; v1 *= ss.y; v2 *= ss.x; v3 *= ss.y;
            }
            if (OUT_SPLIT) {
                bf16 h0, l0, h1, l1;
                bsplit(v0, h0, l0); bsplit(v1, h1, l1);
                *(bf162*)(Ch + (size_t)r0 * N + col) = __halves2bfloat162(h0, h1);
                *(bf162*)(Cl + (size_t)r0 * N + col) = __halves2bfloat162(l0, l1);
                bsplit(v2, h0, l0); bsplit(v3, h1, l1);
                *(bf162*)(Ch + (size_t)r1 * N + col) = __halves2bfloat162(h0, h1);
                *(bf162*)(Cl + (size_t)r1 * N + col) = __halves2bfloat162(l0, l1);
            } else {
                *(float2*)(Cf + (size_t)r0 * N + col) = make_float2(v0, v1);
                *(float2*)(Cf + (size_t)r1 * N + col) = make_float2(v2, v3);
            }
        }
    }
}

// ---------------- softmax over L=256; writes bf16-split attn ----------------
__global__ __launch_bounds__(256)
void softmax256()
{
    const float* logits = (const float*)(g_pool + OFF_LOGITS);
    bf16* atth = (bf16*)(g_pool + OFF_ATTH);
    bf16* attl = (bf16*)(g_pool + OFF_ATTL);

    const int row = blockIdx.x * 8 + threadIdx.y;
    const int lane = threadIdx.x;
    const float* r = logits + (size_t)row * LL;

    float v[8];
    float mx = -1e30f;
    #pragma unroll
    for (int j = 0; j < 8; j++) {
        v[j] = r[lane + 32 * j];
        mx = fmaxf(mx, v[j]);
    }
    #pragma unroll
    for (int s = 16; s > 0; s >>= 1)
        mx = fmaxf(mx, __shfl_xor_sync(0xffffffff, mx, s));

    float sum = 0.0f;
    #pragma unroll
    for (int j = 0; j < 8; j++) {
        v[j] = __expf(v[j] - mx);
        sum += v[j];
    }
    #pragma unroll
    for (int s = 16; s > 0; s >>= 1)
        sum += __shfl_xor_sync(0xffffffff, sum, s);

    const float inv = 1.0f / sum;
    const size_t ro = (size_t)row * LL;
    #pragma unroll
    for (int j = 0; j < 8; j++) {
        float p = v[j] * inv;
        bf16 h, l;
        bsplit(p, h, l);
        atth[ro + lane + 32 * j] = h;
        attl[ro + lane + 32 * j] = l;
    }
}

// ---------------- fusion: sum_s it[b,s,c] * w[b,s,c] ------------------------
__global__ __launch_bounds__(512)
void fusion_partial()
{
    const float* it = (const float*)(g_pool + OFF_IT);
    const float* w  = (const float*)(g_pool + OFF_W);
    float* fp = (float*)(g_pool + OFF_FP);

    const int b = blockIdx.x, ns = blockIdx.y, cidx = threadIdx.x;
    size_t base = ((size_t)b * SS + (size_t)ns * 64) * CC + cidx;
    float acc = 0.0f;
    #pragma unroll 4
    for (int s = 0; s < 64; s++)
        acc += it[base + (size_t)s * CC] * w[base + (size_t)s * CC];
    fp[((size_t)b * 32 + ns) * CC + cidx] = acc;
}

__global__ __launch_bounds__(512)
void fusion_reduce()
{
    const float* fp = (const float*)(g_pool + OFF_FP);
    float* fu = (float*)(g_pool + OFF_FU);
    const int b = blockIdx.x, cidx = threadIdx.x;
    float acc = 0.0f;
    #pragma unroll
    for (int ns = 0; ns < 32; ns++)
        acc += fp[((size_t)b * 32 + ns) * CC + cidx];
    fu[(size_t)b * CC + cidx] = acc;
}

// ---------------- final: out[b,h] = sum_c fusion[b,c] * Wp[h,c] -------------
__global__ __launch_bounds__(256)
void final_gemm(const float* __restrict__ Wp, float* __restrict__ out)
{
    __shared__ float fs[CC];
    const float* fu = (const float*)(g_pool + OFF_FU);
    const int b = blockIdx.x;
    const int h = blockIdx.y * 256 + threadIdx.x;

    for (int i = threadIdx.x; i < CC; i += 256)
        fs[i] = fu[(size_t)b * CC + i];
    __syncthreads();

    float acc = 0.0f;
    const float4* wp4 = (const float4*)(Wp + (size_t)h * CC);
    const float4* fs4 = (const float4*)fs;
    #pragma unroll 4
    for (int c4 = 0; c4 < CC / 4; c4++) {
        float4 w = wp4[c4], f = fs4[c4];
        acc += w.x * f.x + w.y * f.y + w.z * f.z + w.w * f.w;
    }
    out[(size_t)b * HH + h] = acc;
}

// ---------------- launch ----------------------------------------------------
extern "C" void kernel_launch(void* const* d_in, const int* in_sizes, int n_in,
                              void* d_out, int out_size)
{
    const float* x   = (const float*)d_in[0];
    const float* lab = (const float*)d_in[1];
    const float* Wi  = (const float*)d_in[2];
    const float* bi  = (const float*)d_in[3];
    const float* Wl  = (const float*)d_in[4];
    const float* bl  = (const float*)d_in[5];
    const float* Wia = (const float*)d_in[6];
    const float* bia = (const float*)d_in[7];
    const float* Wla = (const float*)d_in[8];
    const float* bla = (const float*)d_in[9];
    const float* ctx = (const float*)d_in[10];
    const float* Wp  = (const float*)d_in[11];
    float* out = (float*)d_out;

    cudaFuncSetAttribute(mma_gemm<EPI_SIGR, true>,        cudaFuncAttributeMaxDynamicSharedMemorySize, GSMEM);
    cudaFuncSetAttribute(mma_gemm<EPI_SIGC, true>,        cudaFuncAttributeMaxDynamicSharedMemorySize, GSMEM);
    cudaFuncSetAttribute(mma_gemm<EPI_SIGC, false>,       cudaFuncAttributeMaxDynamicSharedMemorySize, GSMEM);
    cudaFuncSetAttribute(mma_gemm<EPI_SIGC_SCALE, true>,  cudaFuncAttributeMaxDynamicSharedMemorySize, GSMEM);
    cudaFuncSetAttribute(mma_gemm<EPI_NONE, false>,       cudaFuncAttributeMaxDynamicSharedMemorySize, GSMEM);

    // ---- input splits (5 launches, indices 0..4) ----
    ksplit<<<(MROWS * HH / 4 + 255) / 256, 256>>>((const float4*)x,   OFF_XH,   OFF_XL,   MROWS * HH / 4);
    ksplit<<<(LL * HH / 4 + 255) / 256, 256>>>((const float4*)lab, OFF_LABH, OFF_LABL, LL * HH / 4);
    ksplit<<<(CC * HH / 4 + 255) / 256, 256>>>((const float4*)Wi,  OFF_WIH,  OFF_WIL,  CC * HH / 4);
    ksplit<<<(CC * HH / 4 + 255) / 256, 256>>>((const float4*)Wl,  OFF_WLH,  OFF_WLL,  CC * HH / 4);
    ksplit<<<(CC * HH / 4 + 255) / 256, 256>>>((const float4*)Wia, OFF_WIAH, OFF_WIAL, CC * HH / 4);

    // ---- G3 as launch index 5 so ncu (-s 5 -c 1) captures the big GEMM ----
    // G3: it = sigmoid(x @ Wi^T + bi)  fp32 [32768,512], K=768
    mma_gemm<EPI_SIGC, false><<<dim3(CC / 128, MROWS / 128), 256, GSMEM>>>(
        OFF_XH, OFF_XL, OFF_WIH, OFF_WIL, OFF_IT, 0, 0, MROWS, CC, HH, bi, nullptr);

    // remaining split
    ksplit<<<(CC * HH / 4 + 255) / 256, 256>>>((const float4*)Wla, OFF_WLAH, OFF_WLAL, CC * HH / 4);

    // ---- G1: ltT[c,l] = sigmoid(Wl @ lab^T + bl[row])  [512,256], K=768 ----
    mma_gemm<EPI_SIGR, true><<<dim3(LL / 128, CC / 128), 256, GSMEM>>>(
        OFF_WLH, OFF_WLL, OFF_LABH, OFF_LABL, 0, OFF_LTH, OFF_LTL, CC, LL, HH, bl, nullptr);

    // ---- G2: la[l,c] = sigmoid(lab @ Wla^T + bla[col]) [256,512], K=768 ----
    mma_gemm<EPI_SIGC, true><<<dim3(CC / 128, LL / 128), 256, GSMEM>>>(
        OFF_LABH, OFF_LABL, OFF_WLAH, OFF_WLAL, 0, OFF_LAH, OFF_LAL, LL, CC, HH, bla, nullptr);

    // ---- G4: ia' = sigmoid(x @ Wia^T + bia) * ctx  split [32768,512], K=768 ----
    mma_gemm<EPI_SIGC_SCALE, true><<<dim3(CC / 128, MROWS / 128), 256, GSMEM>>>(
        OFF_XH, OFF_XL, OFF_WIAH, OFF_WIAL, 0, OFF_IAH, OFF_IAL, MROWS, CC, HH, bia, ctx);

    // ---- G5: logits = ia' @ la^T  fp32 [32768,256], K=512 ----
    mma_gemm<EPI_NONE, false><<<dim3(LL / 128, MROWS / 128), 256, GSMEM>>>(
        OFF_IAH, OFF_IAL, OFF_LAH, OFF_LAL, OFF_LOGITS, 0, 0, MROWS, LL, CC, nullptr, nullptr);

    // ---- softmax -> attn split ----
    softmax256<<<MROWS / 8, dim3(32, 8)>>>();

    // ---- G7: weighted = attn @ ltT^T  fp32 [32768,512], K=256 ----
    mma_gemm<EPI_NONE, false><<<dim3(CC / 128, MROWS / 128), 256, GSMEM>>>(
        OFF_ATTH, OFF_ATTL, OFF_LTH, OFF_LTL, OFF_W, 0, 0, MROWS, CC, LL, nullptr, nullptr);

    // ---- fusion + final projection ----
    fusion_partial<<<dim3(BB, 32), 512>>>();
    fusion_reduce<<<BB, 512>>>();
    final_gemm<<<dim3(BB, HH / 256), 256>>>(Wp, out);
}

// round 8
// speedup vs baseline: 2.8052x; 1.0869x over previous
#include <cuda_runtime.h>
#include <cuda_bf16.h>
#include <cstdint>
#include <cstddef>

// Problem dims (fixed)
#define BB 16
#define SS 2048
#define LL 256
#define HH 768
#define CC 512
#define MROWS (BB*SS)   // 32768

typedef __nv_bfloat16  bf16;
typedef __nv_bfloat162 bf162;

// ---------------- one static scratch pool, byte-addressed -------------------
constexpr size_t SZ_IT     = (size_t)MROWS * CC * 4;
constexpr size_t SZ_LOGITS = (size_t)MROWS * LL * 4;
constexpr size_t SZ_W      = (size_t)MROWS * CC * 4;
constexpr size_t SZ_FP     = (size_t)BB * 32 * CC * 4;
constexpr size_t SZ_FU     = (size_t)BB * CC * 4;
constexpr size_t SZ_X2     = (size_t)MROWS * HH * 2;
constexpr size_t SZ_LAB2   = (size_t)LL * HH * 2;
constexpr size_t SZ_WT2    = (size_t)CC * HH * 2;
constexpr size_t SZ_IA2    = (size_t)MROWS * CC * 2;
constexpr size_t SZ_ATT2   = (size_t)MROWS * LL * 2;
constexpr size_t SZ_LC2    = (size_t)LL * CC * 2;

constexpr size_t OFF_IT     = 0;
constexpr size_t OFF_LOGITS = OFF_IT + SZ_IT;
constexpr size_t OFF_W      = OFF_LOGITS + SZ_LOGITS;
constexpr size_t OFF_FP     = OFF_W + SZ_W;
constexpr size_t OFF_FU     = OFF_FP + SZ_FP;
constexpr size_t OFF_XH     = OFF_FU + SZ_FU;
constexpr size_t OFF_XL     = OFF_XH + SZ_X2;
constexpr size_t OFF_LABH   = OFF_XL + SZ_X2;
constexpr size_t OFF_LABL   = OFF_LABH + SZ_LAB2;
constexpr size_t OFF_WIH    = OFF_LABL + SZ_LAB2;
constexpr size_t OFF_WIL    = OFF_WIH + SZ_WT2;
constexpr size_t OFF_WLH    = OFF_WIL + SZ_WT2;
constexpr size_t OFF_WLL    = OFF_WLH + SZ_WT2;
constexpr size_t OFF_WIAH   = OFF_WLL + SZ_WT2;
constexpr size_t OFF_WIAL   = OFF_WIAH + SZ_WT2;
constexpr size_t OFF_WLAH   = OFF_WIAL + SZ_WT2;
constexpr size_t OFF_WLAL   = OFF_WLAH + SZ_WT2;
constexpr size_t OFF_IAH    = OFF_WLAL + SZ_WT2;
constexpr size_t OFF_IAL    = OFF_IAH + SZ_IA2;
constexpr size_t OFF_ATTH   = OFF_IAL + SZ_IA2;
constexpr size_t OFF_ATTL   = OFF_ATTH + SZ_ATT2;
constexpr size_t OFF_LTH    = OFF_ATTL + SZ_ATT2;
constexpr size_t OFF_LTL    = OFF_LTH + SZ_LC2;
constexpr size_t OFF_LAH    = OFF_LTL + SZ_LC2;
constexpr size_t OFF_LAL    = OFF_LAH + SZ_LC2;
constexpr size_t POOL_BYTES = OFF_LAL + SZ_LC2;

__device__ __align__(16) unsigned char g_pool[POOL_BYTES];

// ---------------- helpers ---------------------------------------------------
__device__ __forceinline__ uint32_t smem_u32(const void* p) {
    uint32_t a;
    asm("{ .reg .u64 t; cvta.to.shared.u64 t, %1; cvt.u32.u64 %0, t; }" : "=r"(a) : "l"(p));
    return a;
}
__device__ __forceinline__ void cp16(uint32_t dst, const void* src) {
    asm volatile("cp.async.cg.shared.global [%0], [%1], 16;" :: "r"(dst), "l"(src) : "memory");
}
// one 32-byte slot = two 16-byte cp.async
__device__ __forceinline__ void cp32(uint32_t dst, const bf16* src) {
    cp16(dst, src);
    cp16(dst + 16, src + 8);
}
#define CP_COMMIT() asm volatile("cp.async.commit_group;" ::: "memory")
#define CP_WAIT0()  asm volatile("cp.async.wait_group 0;"  ::: "memory")

#define LDSM4(R0,R1,R2,R3,ADDR) \
    asm volatile("ldmatrix.sync.aligned.m8n8.x4.shared.b16 {%0,%1,%2,%3}, [%4];" \
                 : "=r"(R0),"=r"(R1),"=r"(R2),"=r"(R3) : "r"(ADDR))

#define MMA_BF16(C,A,B0,B1) \
    asm volatile("mma.sync.aligned.m16n8k16.row.col.f32.bf16.bf16.f32 " \
                 "{%0,%1,%2,%3},{%4,%5,%6,%7},{%8,%9},{%0,%1,%2,%3};" \
                 : "+f"((C)[0]),"+f"((C)[1]),"+f"((C)[2]),"+f"((C)[3]) \
                 : "r"((A)[0]),"r"((A)[1]),"r"((A)[2]),"r"((A)[3]), \
                   "r"(B0),"r"(B1))

__device__ __forceinline__ void bsplit(float v, bf16& h, bf16& l) {
    h = __float2bfloat16(v);
    l = __float2bfloat16(v - __bfloat162float(h));
}
__device__ __forceinline__ float sigmoidf_(float v) {
    return 1.0f / (1.0f + __expf(-v));
}

// ---------------- fp32 -> bf16 hi/lo split ----------------------------------
__global__ __launch_bounds__(256)
void ksplit(const float4* __restrict__ src, size_t oHi, size_t oLo, int n4)
{
    int i = blockIdx.x * 256 + threadIdx.x;
    if (i >= n4) return;
    bf162* hi = (bf162*)(g_pool + oHi);
    bf162* lo = (bf162*)(g_pool + oLo);
    float4 v = src[i];
    bf16 h0, l0, h1, l1, h2, l2, h3, l3;
    bsplit(v.x, h0, l0); bsplit(v.y, h1, l1);
    bsplit(v.z, h2, l2); bsplit(v.w, h3, l3);
    hi[i * 2 + 0] = __halves2bfloat162(h0, h1);
    hi[i * 2 + 1] = __halves2bfloat162(h2, h3);
    lo[i * 2 + 0] = __halves2bfloat162(l0, l1);
    lo[i * 2 + 1] = __halves2bfloat162(l2, l3);
}

// ---------------- shared tile geometry ---------------------------------------
#define SROW  80            // smem bytes per 32-bf16 row (64B data + 16B pad)
#define TILEB (128 * SROW)  // 10240

enum { EPI_NONE = 0, EPI_SIGC = 1, EPI_SIGC_SCALE = 2, EPI_SIGR = 3 };

// ---------------- single-output bf16(-split) mma GEMM ------------------------
// C[M,N] = epi( A @ B^T ). NPROD=3: hi*hi+hi*lo+lo*hi. NPROD=1: hi*hi only.
#define STAGEB (4 * TILEB)
#define GSMEM (2 * STAGEB)  // 81920

template<int EPI, bool OUT_SPLIT, int NPROD>
__global__ __launch_bounds__(256, 2)
void mma_gemm(size_t oAh, size_t oAl, size_t oBh, size_t oBl,
              size_t oCf, size_t oCh, size_t oCl,
              int M, int N, int K,
              const float* __restrict__ bias, const float* __restrict__ scale)
{
    const bf16* Ah = (const bf16*)(g_pool + oAh);
    const bf16* Al = (const bf16*)(g_pool + oAl);
    const bf16* Bh = (const bf16*)(g_pool + oBh);
    const bf16* Bl = (const bf16*)(g_pool + oBl);
    float* Cf = (float*)(g_pool + oCf);
    bf16* Ch  = (bf16*)(g_pool + oCh);
    bf16* Cl  = (bf16*)(g_pool + oCl);

    extern __shared__ char smem[];
    const uint32_t sb = smem_u32(smem);
    const int tid  = threadIdx.x;
    const int lane = tid & 31;
    const int wid  = tid >> 5;
    const int wm   = wid & 3;
    const int wn   = wid >> 2;
    const int m0 = blockIdx.y * 128;
    const int n0 = blockIdx.x * 128;

    const int lr = tid >> 1;
    const int lh = tid & 1;
    const bf16* gAh = Ah + (size_t)(m0 + lr) * K + lh * 16;
    const bf16* gAl = Al + (size_t)(m0 + lr) * K + lh * 16;
    const bf16* gBh = Bh + (size_t)(n0 + lr) * K + lh * 16;
    const bf16* gBl = Bl + (size_t)(n0 + lr) * K + lh * 16;
    const uint32_t sdst = (uint32_t)(lr * SROW + lh * 32);

    const int NCH = K / 32;
    float c[2][8][4] = {};

    {
        uint32_t d = sb + sdst;
        cp32(d,             gAh);
        cp32(d + 2 * TILEB, gBh);
        if (NPROD == 3) {
            cp32(d + TILEB,     gAl);
            cp32(d + 3 * TILEB, gBl);
        }
        CP_COMMIT();
        CP_WAIT0();
        __syncthreads();
    }

    for (int ch = 0; ch < NCH; ch++) {
        if (ch + 1 < NCH) {
            const int k0 = (ch + 1) * 32;
            uint32_t d = sb + ((ch + 1) & 1) * STAGEB + sdst;
            cp32(d,             gAh + k0);
            cp32(d + 2 * TILEB, gBh + k0);
            if (NPROD == 3) {
                cp32(d + TILEB,     gAl + k0);
                cp32(d + 3 * TILEB, gBl + k0);
            }
            CP_COMMIT();
        }

        const uint32_t base = sb + (ch & 1) * STAGEB;
        #pragma unroll
        for (int ks = 0; ks < 2; ks++) {
            uint32_t ah[2][4], al[2][4];
            #pragma unroll
            for (int mf = 0; mf < 2; mf++) {
                uint32_t addr = base
                    + (uint32_t)((wm * 32 + mf * 16 + (lane & 15)) * SROW)
                    + (uint32_t)(ks * 32 + (lane >> 4) * 16);
                LDSM4(ah[mf][0], ah[mf][1], ah[mf][2], ah[mf][3], addr);
                if (NPROD == 3)
                    LDSM4(al[mf][0], al[mf][1], al[mf][2], al[mf][3], addr + TILEB);
            }
            const int g = lane >> 3;
            #pragma unroll
            for (int p = 0; p < 4; p++) {
                uint32_t addr = base + 2 * TILEB
                    + (uint32_t)((wn * 64 + p * 16 + ((g & 2) ? 8 : 0) + (lane & 7)) * SROW)
                    + (uint32_t)(ks * 32 + (g & 1) * 16);
                uint32_t h0, h1, h2, h3;
                LDSM4(h0, h1, h2, h3, addr);
                if (NPROD == 3) {
                    uint32_t l0, l1, l2, l3;
                    LDSM4(l0, l1, l2, l3, addr + TILEB);
                    #pragma unroll
                    for (int mf = 0; mf < 2; mf++) {
                        MMA_BF16(c[mf][2*p],   ah[mf], h0, h1);
                        MMA_BF16(c[mf][2*p],   ah[mf], l0, l1);
                        MMA_BF16(c[mf][2*p],   al[mf], h0, h1);
                        MMA_BF16(c[mf][2*p+1], ah[mf], h2, h3);
                        MMA_BF16(c[mf][2*p+1], ah[mf], l2, l3);
                        MMA_BF16(c[mf][2*p+1], al[mf], h2, h3);
                    }
                } else {
                    #pragma unroll
                    for (int mf = 0; mf < 2; mf++) {
                        MMA_BF16(c[mf][2*p],   ah[mf], h0, h1);
                        MMA_BF16(c[mf][2*p+1], ah[mf], h2, h3);
                    }
                }
            }
        }
        if (ch + 1 < NCH) CP_WAIT0();
        __syncthreads();
    }

    const int quad = lane >> 2;
    const int tq   = lane & 3;
    #pragma unroll
    for (int mf = 0; mf < 2; mf++) {
        const int r0 = m0 + wm * 32 + mf * 16 + quad;
        const int r1 = r0 + 8;
        float rb0 = 0.f, rb1 = 0.f;
        if (EPI == EPI_SIGR) { rb0 = bias[r0]; rb1 = bias[r1]; }
        #pragma unroll
        for (int nf = 0; nf < 8; nf++) {
            const int col = n0 + wn * 64 + nf * 8 + tq * 2;
            float v0 = c[mf][nf][0], v1 = c[mf][nf][1];
            float v2 = c[mf][nf][2], v3 = c[mf][nf][3];
            if (EPI == EPI_SIGC || EPI == EPI_SIGC_SCALE) {
                float2 bb = *(const float2*)(bias + col);
                v0 = sigmoidf_(v0 + bb.x); v1 = sigmoidf_(v1 + bb.y);
                v2 = sigmoidf_(v2 + bb.x); v3 = sigmoidf_(v3 + bb.y);
            } else if (EPI == EPI_SIGR) {
                v0 = sigmoidf_(v0 + rb0); v1 = sigmoidf_(v1 + rb0);
                v2 = sigmoidf_(v2 + rb1); v3 = sigmoidf_(v3 + rb1);
            }
            if (EPI == EPI_SIGC_SCALE) {
                float2 ss = *(const float2*)(scale + col);
                v0 *= ss.x; v1 *= ss.y; v2 *= ss.x; v3 *= ss.y;
            }
            if (OUT_SPLIT) {
                bf16 h0, l0, h1, l1;
                bsplit(v0, h0, l0); bsplit(v1, h1, l1);
                *(bf162*)(Ch + (size_t)r0 * N + col) = __halves2bfloat162(h0, h1);
                *(bf162*)(Cl + (size_t)r0 * N + col) = __halves2bfloat162(l0, l1);
                bsplit(v2, h0, l0); bsplit(v3, h1, l1);
                *(bf162*)(Ch + (size_t)r1 * N + col) = __halves2bfloat162(h0, h1);
                *(bf162*)(Cl + (size_t)r1 * N + col) = __halves2bfloat162(l0, l1);
            } else {
                *(float2*)(Cf + (size_t)r0 * N + col) = make_float2(v0, v1);
                *(float2*)(Cf + (size_t)r1 * N + col) = make_float2(v2, v3);
            }
        }
    }
}

// ---------------- fused dual GEMM: it + ia' from shared A --------------------
// 512 threads. Warps 0-7 -> it = sigmoid(x@Wi^T+bi) (fp32 out).
// Warps 8-15 -> ia' = sigmoid(x@Wia^T+bia)*ctx (split out).
// smem/stage: [Ah, Al, B0h, B0l, B1h, B1l] x TILEB; 2 stages.
#define DSTAGEB (6 * TILEB)       // 61440
#define DGSMEM  (2 * DSTAGEB)     // 122880

__global__ __launch_bounds__(512, 1)
void mma_gemm_dual(const float* __restrict__ bias_i,
                   const float* __restrict__ bias_ia,
                   const float* __restrict__ ctx)
{
    extern __shared__ char smem[];
    const uint32_t sb = smem_u32(smem);
    const int tid  = threadIdx.x;
    const int lane = tid & 31;
    const int wid  = tid >> 5;
    const int wg   = wid >> 3;        // 0: it, 1: ia
    const int wl   = wid & 7;
    const int wm   = wl & 3;
    const int wn   = wl >> 2;
    const int m0 = blockIdx.y * 128;
    const int n0 = blockIdx.x * 128;
    const int K = HH;

    // per-thread loader slots: 3 chunks of 32B each
    const bf16* srcp[3];
    uint32_t dstp[3];
    {
        const bf16* baseA_h = (const bf16*)(g_pool + OFF_XH);
        const bf16* baseA_l = (const bf16*)(g_pool + OFF_XL);
        const bf16* baseB0h = (const bf16*)(g_pool + OFF_WIH);
        const bf16* baseB0l = (const bf16*)(g_pool + OFF_WIL);
        const bf16* baseB1h = (const bf16*)(g_pool + OFF_WIAH);
        const bf16* baseB1l = (const bf16*)(g_pool + OFF_WIAL);
        #pragma unroll
        for (int t = 0; t < 3; t++) {
            int chunk = tid + t * 512;
            int tile = chunk >> 8;          // 0..5
            int pos  = chunk & 255;
            int row  = pos >> 1;
            int half = pos & 1;
            const bf16* bp;
            int rbase;
            switch (tile) {
                case 0: bp = baseA_h; rbase = m0; break;
                case 1: bp = baseA_l; rbase = m0; break;
                case 2: bp = baseB0h; rbase = n0; break;
                case 3: bp = baseB0l; rbase = n0; break;
                case 4: bp = baseB1h; rbase = n0; break;
                default: bp = baseB1l; rbase = n0; break;
            }
            srcp[t] = bp + (size_t)(rbase + row) * K + half * 16;
            dstp[t] = (uint32_t)(tile * TILEB + row * SROW + half * 32);
        }
    }

    const int NCH = K / 32;
    float c[2][8][4] = {};

    {
        #pragma unroll
        for (int t = 0; t < 3; t++)
            cp32(sb + dstp[t], srcp[t]);
        CP_COMMIT();
        CP_WAIT0();
        __syncthreads();
    }

    // B base offset for this warp-group
    const uint32_t bofs = (uint32_t)((2 + 2 * wg) * TILEB);

    for (int ch = 0; ch < NCH; ch++) {
        if (ch + 1 < NCH) {
            const int k0 = (ch + 1) * 32;
            const uint32_t stg = sb + ((ch + 1) & 1) * DSTAGEB;
            #pragma unroll
            for (int t = 0; t < 3; t++)
                cp32(stg + dstp[t], srcp[t] + k0);
            CP_COMMIT();
        }

        const uint32_t base = sb + (ch & 1) * DSTAGEB;
        #pragma unroll
        for (int ks = 0; ks < 2; ks++) {
            uint32_t ah[2][4], al[2][4];
            #pragma unroll
            for (int mf = 0; mf < 2; mf++) {
                uint32_t addr = base
                    + (uint32_t)((wm * 32 + mf * 16 + (lane & 15)) * SROW)
                    + (uint32_t)(ks * 32 + (lane >> 4) * 16);
                LDSM4(ah[mf][0], ah[mf][1], ah[mf][2], ah[mf][3], addr);
                LDSM4(al[mf][0], al[mf][1], al[mf][2], al[mf][3], addr + TILEB);
            }
            const int g = lane >> 3;
            #pragma unroll
            for (int p = 0; p < 4; p++) {
                uint32_t addr = base + bofs
                    + (uint32_t)((wn * 64 + p * 16 + ((g & 2) ? 8 : 0) + (lane & 7)) * SROW)
                    + (uint32_t)(ks * 32 + (g & 1) * 16);
                uint32_t h0, h1, h2, h3, l0, l1, l2, l3;
                LDSM4(h0, h1, h2, h3, addr);
                LDSM4(l0, l1, l2, l3, addr + TILEB);
                #pragma unroll
                for (int mf = 0; mf < 2; mf++) {
                    MMA_BF16(c[mf][2*p],   ah[mf], h0, h1);
                    MMA_BF16(c[mf][2*p],   ah[mf], l0, l1);
                    MMA_BF16(c[mf][2*p],   al[mf], h0, h1);
                    MMA_BF16(c[mf][2*p+1], ah[mf], h2, h3);
                    MMA_BF16(c[mf][2*p+1], ah[mf], l2, l3);
                    MMA_BF16(c[mf][2*p+1], al[mf], h2, h3);
                }
            }
        }
        if (ch + 1 < NCH) CP_WAIT0();
        __syncthreads();
    }

    // epilogues
    const int quad = lane >> 2;
    const int tq   = lane & 3;
    if (wg == 0) {
        float* Cf = (float*)(g_pool + OFF_IT);
        #pragma unroll
        for (int mf = 0; mf < 2; mf++) {
            const int r0 = m0 + wm * 32 + mf * 16 + quad;
            const int r1 = r0 + 8;
            #pragma unroll
            for (int nf = 0; nf < 8; nf++) {
                const int col = n0 + wn * 64 + nf * 8 + tq * 2;
                float2 bb = *(const float2*)(bias_i + col);
                float v0 = sigmoidf_(c[mf][nf][0] + bb.x);
                float v1 = sigmoidf_(c[mf][nf][1] + bb.y);
                float v2 = sigmoidf_(c[mf][nf][2] + bb.x);
                float v3 = sigmoidf_(c[mf][nf][3] + bb.y);
                *(float2*)(Cf + (size_t)r0 * CC + col) = make_float2(v0, v1);
                *(float2*)(Cf + (size_t)r1 * CC + col) = make_float2(v2, v3);
            }
        }
    } else {
        bf16* Ch = (bf16*)(g_pool + OFF_IAH);
        bf16* Cl = (bf16*)(g_pool + OFF_IAL);
        #pragma unroll
        for (int mf = 0; mf < 2; mf++) {
            const int r0 = m0 + wm * 32 + mf * 16 + quad;
            const int r1 = r0 + 8;
            #pragma unroll
            for (int nf = 0; nf < 8; nf++) {
                const int col = n0 + wn * 64 + nf * 8 + tq * 2;
                float2 bb = *(const float2*)(bias_ia + col);
                float2 ss = *(const float2*)(ctx + col);
                float v0 = sigmoidf_(c[mf][nf][0] + bb.x) * ss.x;
                float v1 = sigmoidf_(c[mf][nf][1] + bb.y) * ss.y;
                float v2 = sigmoidf_(c[mf][nf][2] + bb.x) * ss.x;
                float v3 = sigmoidf_(c[mf][nf][3] + bb.y) * ss.y;
                bf16 h0, l0, h1, l1;
                bsplit(v0, h0, l0); bsplit(v1, h1, l1);
                *(bf162*)(Ch + (size_t)r0 * CC + col) = __halves2bfloat162(h0, h1);
                *(bf162*)(Cl + (size_t)r0 * CC + col) = __halves2bfloat162(l0, l1);
                bsplit(v2, h0, l0); bsplit(v3, h1, l1);
                *(bf162*)(Ch + (size_t)r1 * CC + col) = __halves2bfloat162(h0, h1);
                *(bf162*)(Cl + (size_t)r1 * CC + col) = __halves2bfloat162(l0, l1);
            }
        }
    }
}

// ---------------- softmax over L=256; writes bf16 attn (hi only) -------------
__global__ __launch_bounds__(256)
void softmax256()
{
    const float* logits = (const float*)(g_pool + OFF_LOGITS);
    bf16* atth = (bf16*)(g_pool + OFF_ATTH);

    const int row = blockIdx.x * 8 + threadIdx.y;
    const int lane = threadIdx.x;
    const float* r = logits + (size_t)row * LL;

    float v[8];
    float mx = -1e30f;
    #pragma unroll
    for (int j = 0; j < 8; j++) {
        v[j] = r[lane + 32 * j];
        mx = fmaxf(mx, v[j]);
    }
    #pragma unroll
    for (int s = 16; s > 0; s >>= 1)
        mx = fmaxf(mx, __shfl_xor_sync(0xffffffff, mx, s));

    float sum = 0.0f;
    #pragma unroll
    for (int j = 0; j < 8; j++) {
        v[j] = __expf(v[j] - mx);
        sum += v[j];
    }
    #pragma unroll
    for (int s = 16; s > 0; s >>= 1)
        sum += __shfl_xor_sync(0xffffffff, sum, s);

    const float inv = 1.0f / sum;
    const size_t ro = (size_t)row * LL;
    #pragma unroll
    for (int j = 0; j < 8; j++)
        atth[ro + lane + 32 * j] = __float2bfloat16(v[j] * inv);
}

// ---------------- fusion: sum_s it[b,s,c] * w[b,s,c] ------------------------
__global__ __launch_bounds__(512)
void fusion_partial()
{
    const float* it = (const float*)(g_pool + OFF_IT);
    const float* w  = (const float*)(g_pool + OFF_W);
    float* fp = (float*)(g_pool + OFF_FP);

    const int b = blockIdx.x, ns = blockIdx.y, cidx = threadIdx.x;
    size_t base = ((size_t)b * SS + (size_t)ns * 64) * CC + cidx;
    float acc = 0.0f;
    #pragma unroll 4
    for (int s = 0; s < 64; s++)
        acc += it[base + (size_t)s * CC] * w[base + (size_t)s * CC];
    fp[((size_t)b * 32 + ns) * CC + cidx] = acc;
}

__global__ __launch_bounds__(512)
void fusion_reduce()
{
    const float* fp = (const float*)(g_pool + OFF_FP);
    float* fu = (float*)(g_pool + OFF_FU);
    const int b = blockIdx.x, cidx = threadIdx.x;
    float acc = 0.0f;
    #pragma unroll
    for (int ns = 0; ns < 32; ns++)
        acc += fp[((size_t)b * 32 + ns) * CC + cidx];
    fu[(size_t)b * CC + cidx] = acc;
}

// ---------------- final: out[b,h] = sum_c fusion[b,c] * Wp[h,c] -------------
__global__ __launch_bounds__(256)
void final_gemm(const float* __restrict__ Wp, float* __restrict__ out)
{
    __shared__ float fs[CC];
    const float* fu = (const float*)(g_pool + OFF_FU);
    const int b = blockIdx.x;
    const int h = blockIdx.y * 256 + threadIdx.x;

    for (int i = threadIdx.x; i < CC; i += 256)
        fs[i] = fu[(size_t)b * CC + i];
    __syncthreads();

    float acc = 0.0f;
    const float4* wp4 = (const float4*)(Wp + (size_t)h * CC);
    const float4* fs4 = (const float4*)fs;
    #pragma unroll 4
    for (int c4 = 0; c4 < CC / 4; c4++) {
        float4 w = wp4[c4], f = fs4[c4];
        acc += w.x * f.x + w.y * f.y + w.z * f.z + w.w * f.w;
    }
    out[(size_t)b * HH + h] = acc;
}

// ---------------- launch ----------------------------------------------------
extern "C" void kernel_launch(void* const* d_in, const int* in_sizes, int n_in,
                              void* d_out, int out_size)
{
    const float* x   = (const float*)d_in[0];
    const float* lab = (const float*)d_in[1];
    const float* Wi  = (const float*)d_in[2];
    const float* bi  = (const float*)d_in[3];
    const float* Wl  = (const float*)d_in[4];
    const float* bl  = (const float*)d_in[5];
    const float* Wia = (const float*)d_in[6];
    const float* bia = (const float*)d_in[7];
    const float* Wla = (const float*)d_in[8];
    const float* bla = (const float*)d_in[9];
    const float* ctx = (const float*)d_in[10];
    const float* Wp  = (const float*)d_in[11];
    float* out = (float*)d_out;

    cudaFuncSetAttribute(mma_gemm<EPI_SIGR, true, 3>,  cudaFuncAttributeMaxDynamicSharedMemorySize, GSMEM);
    cudaFuncSetAttribute(mma_gemm<EPI_SIGC, true, 3>,  cudaFuncAttributeMaxDynamicSharedMemorySize, GSMEM);
    cudaFuncSetAttribute(mma_gemm<EPI_NONE, false, 3>, cudaFuncAttributeMaxDynamicSharedMemorySize, GSMEM);
    cudaFuncSetAttribute(mma_gemm<EPI_NONE, false, 1>, cudaFuncAttributeMaxDynamicSharedMemorySize, GSMEM);
    cudaFuncSetAttribute(mma_gemm_dual,                cudaFuncAttributeMaxDynamicSharedMemorySize, DGSMEM);

    // ---- input splits ----
    ksplit<<<(MROWS * HH / 4 + 255) / 256, 256>>>((const float4*)x,   OFF_XH,   OFF_XL,   MROWS * HH / 4);
    ksplit<<<(LL * HH / 4 + 255) / 256, 256>>>((const float4*)lab, OFF_LABH, OFF_LABL, LL * HH / 4);
    ksplit<<<(CC * HH / 4 + 255) / 256, 256>>>((const float4*)Wi,  OFF_WIH,  OFF_WIL,  CC * HH / 4);
    ksplit<<<(CC * HH / 4 + 255) / 256, 256>>>((const float4*)Wl,  OFF_WLH,  OFF_WLL,  CC * HH / 4);
    ksplit<<<(CC * HH / 4 + 255) / 256, 256>>>((const float4*)Wia, OFF_WIAH, OFF_WIAL, CC * HH / 4);
    ksplit<<<(CC * HH / 4 + 255) / 256, 256>>>((const float4*)Wla, OFF_WLAH, OFF_WLAL, CC * HH / 4);

    // ---- fused G3+G4: it (fp32) and ia' (split) from shared A ----
    mma_gemm_dual<<<dim3(CC / 128, MROWS / 128), 512, DGSMEM>>>(bi, bia, ctx);

    // ---- G1: ltT[c,l] = sigmoid(Wl @ lab^T + bl[row])  [512,256], K=768 ----
    mma_gemm<EPI_SIGR, true, 3><<<dim3(LL / 128, CC / 128), 256, GSMEM>>>(
        OFF_WLH, OFF_WLL, OFF_LABH, OFF_LABL, 0, OFF_LTH, OFF_LTL, CC, LL, HH, bl, nullptr);

    // ---- G2: la[l,c] = sigmoid(lab @ Wla^T + bla[col]) [256,512], K=768 ----
    mma_gemm<EPI_SIGC, true, 3><<<dim3(CC / 128, LL / 128), 256, GSMEM>>>(
        OFF_LABH, OFF_LABL, OFF_WLAH, OFF_WLAL, 0, OFF_LAH, OFF_LAL, LL, CC, HH, bla, nullptr);

    // ---- G5: logits = ia' @ la^T  fp32 [32768,256], K=512 ----
    mma_gemm<EPI_NONE, false, 3><<<dim3(LL / 128, MROWS / 128), 256, GSMEM>>>(
        OFF_IAH, OFF_IAL, OFF_LAH, OFF_LAL, OFF_LOGITS, 0, 0, MROWS, LL, CC, nullptr, nullptr);

    // ---- softmax -> attn (bf16 hi only) ----
    softmax256<<<MROWS / 8, dim3(32, 8)>>>();

    // ---- G7: weighted = attn @ ltT^T  fp32 [32768,512], K=256, 1-product ----
    mma_gemm<EPI_NONE, false, 1><<<dim3(CC / 128, MROWS / 128), 256, GSMEM>>>(
        OFF_ATTH, OFF_ATTH, OFF_LTH, OFF_LTH, OFF_W, 0, 0, MROWS, CC, LL, nullptr, nullptr);

    // ---- fusion + final projection ----
    fusion_partial<<<dim3(BB, 32), 512>>>();
    fusion_reduce<<<BB, 512>>>();
    final_gemm<<<dim3(BB, HH / 256), 256>>>(Wp, out);
}